// round 2
// baseline (speedup 1.0000x reference)
#include <cuda_runtime.h>
#include <cstdint>

// ChempropBlock: V=10000 nodes, E=160000 edges, D=512, DEPTH=3
// out = [node_hiddens (V*D) | eh (E*D)] fp32
//
// Per layer l:
//   nm            = segment_sum(relu(eh), dest)                       (atomic scatter)
//   ehout[m,:]    = ehin[m,:] + (nm[src[m],:] - relu(ehin[rev[m],:])) @ W[l]^T + b[l]
//                   (em computed inside the GEMM A-tile loader; ping-pong buffers)
// Final: node_hiddens = segment_sum(eh, dest)

#define V_N 10000
#define E_N 160000
#define D_N 512
#define DEPTH_N 3

// Scratch (device globals: allocation APIs are banned)
__device__ float g_nm[(size_t)V_N * D_N];          // node messages, 20.5 MB
__device__ float g_eh[(size_t)E_N * D_N];          // ping-pong eh buffer, 327 MB

__device__ __forceinline__ float4 relu4(float4 v) {
    v.x = fmaxf(v.x, 0.f); v.y = fmaxf(v.y, 0.f);
    v.z = fmaxf(v.z, 0.f); v.w = fmaxf(v.w, 0.f);
    return v;
}

// ---------------------------------------------------------------------------
// zero g_nm (references the device symbol directly; no host symbol lookup)
// ---------------------------------------------------------------------------
__global__ void k_zero_nm() {
    int i = blockIdx.x * blockDim.x + threadIdx.x;      // < V*D/4
    ((float4*)g_nm)[i] = make_float4(0.f, 0.f, 0.f, 0.f);
}

__global__ void k_zero_ptr(float4* __restrict__ p, int n4) {
    int i = blockIdx.x * blockDim.x + threadIdx.x;
    if (i < n4) p[i] = make_float4(0.f, 0.f, 0.f, 0.f);
}

// ---------------------------------------------------------------------------
// eh[e,:] = node_feats[src[e],:] + edge_feats[e,:]   (writes scratch g_eh)
// one thread per (edge, 4-float chunk): E*D/4 threads
// ---------------------------------------------------------------------------
__global__ void k_init_eh(const float* __restrict__ nf,
                          const float* __restrict__ ef,
                          const int* __restrict__ src) {
    int idx = blockIdx.x * blockDim.x + threadIdx.x;    // < E*D/4
    int e = idx >> 7;             // D/4 = 128 chunks per edge
    int c = (idx & 127) << 2;
    int s = __ldg(&src[e]);
    const float4 a = *(const float4*)(nf + (size_t)s * D_N + c);
    const float4 b = *(const float4*)(ef + (size_t)e * D_N + c);
    float4 r; r.x = a.x + b.x; r.y = a.y + b.y; r.z = a.z + b.z; r.w = a.w + b.w;
    *(float4*)(g_eh + (size_t)e * D_N + c) = r;
}

// ---------------------------------------------------------------------------
// g_nm[dest[e],:] += relu(ehin[e,:])
// ---------------------------------------------------------------------------
__global__ void k_scatter_relu(const float* __restrict__ ehin,
                               const int* __restrict__ dst) {
    int idx = blockIdx.x * blockDim.x + threadIdx.x;    // < E*D/4
    int e = idx >> 7;
    int c = (idx & 127) << 2;
    float4 v = relu4(*(const float4*)(ehin + (size_t)e * D_N + c));
    int d = __ldg(&dst[e]);
    float* p = g_nm + (size_t)d * D_N + c;
    atomicAdd(p + 0, v.x);
    atomicAdd(p + 1, v.y);
    atomicAdd(p + 2, v.z);
    atomicAdd(p + 3, v.w);
}

// ---------------------------------------------------------------------------
// Fused layer GEMM:
//   ehout[m,n] = ehin[m,n] + bias[n] + sum_k em[m,k] * W[n,k]
//   em[m,k]    = g_nm[src[m],k] - relu(ehin[rev[m],k])     (computed on load)
// 128x128x16 tile, 256 threads, 8x8 per thread, double-buffered smem.
// E (160000) and D (512) divide the tile sizes exactly -> no bounds checks.
// ehin != ehout (ping-pong), so in-flight reads of ehin[rev] are race-free.
// ---------------------------------------------------------------------------
#define BM 128
#define BN 128
#define BK 16

__global__ void __launch_bounds__(256, 2)
k_gemm_layer(const float* __restrict__ W,
             const float* __restrict__ bias,
             const float* __restrict__ ehin,
             float* __restrict__ ehout,
             const int* __restrict__ src,
             const int* __restrict__ rev) {
    __shared__ float As[2][BK][BM + 4];
    __shared__ float Bs[2][BK][BN + 4];

    const int tid = threadIdx.x;
    const int tx = tid & 15;          // 0..15 -> N
    const int ty = tid >> 4;          // 0..15 -> M
    const int mBase = blockIdx.y * BM;
    const int nBase = blockIdx.x * BN;

    const int lr = tid >> 2;          // 0..63 tile row
    const int lc = (tid & 3) << 2;    // 0,4,8,12 float offset (4 threads = 64B run)

    // A-side gather sources for tile rows lr and lr+64
    const int m0 = mBase + lr;
    const int m1 = m0 + 64;
    const int s0 = __ldg(&src[m0]);
    const int r0 = __ldg(&rev[m0]);
    const int s1 = __ldg(&src[m1]);
    const int r1 = __ldg(&rev[m1]);

    const float* A0n = g_nm + (size_t)s0 * D_N + lc;
    const float* A0h = ehin + (size_t)r0 * D_N + lc;
    const float* A1n = g_nm + (size_t)s1 * D_N + lc;
    const float* A1h = ehin + (size_t)r1 * D_N + lc;
    const float* Wp0 = W + (size_t)(nBase + lr) * D_N + lc;
    const float* Wp1 = Wp0 + (size_t)64 * D_N;

    float4 ra0, ra1, rb0, rb1;
    {   // stage kt = 0
        float4 n0 = *(const float4*)(A0n);
        float4 h0 = relu4(*(const float4*)(A0h));
        float4 n1 = *(const float4*)(A1n);
        float4 h1 = relu4(*(const float4*)(A1h));
        ra0.x = n0.x - h0.x; ra0.y = n0.y - h0.y; ra0.z = n0.z - h0.z; ra0.w = n0.w - h0.w;
        ra1.x = n1.x - h1.x; ra1.y = n1.y - h1.y; ra1.z = n1.z - h1.z; ra1.w = n1.w - h1.w;
        rb0 = *(const float4*)(Wp0);
        rb1 = *(const float4*)(Wp1);
    }
#pragma unroll
    for (int i = 0; i < 4; ++i) {
        As[0][lc + i][lr]      = ((const float*)&ra0)[i];
        As[0][lc + i][lr + 64] = ((const float*)&ra1)[i];
        Bs[0][lc + i][lr]      = ((const float*)&rb0)[i];
        Bs[0][lc + i][lr + 64] = ((const float*)&rb1)[i];
    }
    __syncthreads();

    float acc[8][8];
#pragma unroll
    for (int i = 0; i < 8; ++i)
#pragma unroll
        for (int j = 0; j < 8; ++j) acc[i][j] = 0.f;

    const int KT = D_N / BK;    // 32
    int buf = 0;

    for (int kt = 0; kt < KT; ++kt) {
        if (kt + 1 < KT) {
            const int ko = (kt + 1) * BK;
            float4 n0 = *(const float4*)(A0n + ko);
            float4 h0 = relu4(*(const float4*)(A0h + ko));
            float4 n1 = *(const float4*)(A1n + ko);
            float4 h1 = relu4(*(const float4*)(A1h + ko));
            ra0.x = n0.x - h0.x; ra0.y = n0.y - h0.y; ra0.z = n0.z - h0.z; ra0.w = n0.w - h0.w;
            ra1.x = n1.x - h1.x; ra1.y = n1.y - h1.y; ra1.z = n1.z - h1.z; ra1.w = n1.w - h1.w;
            rb0 = *(const float4*)(Wp0 + ko);
            rb1 = *(const float4*)(Wp1 + ko);
        }

#pragma unroll
        for (int k = 0; k < BK; ++k) {
            float a[8], b[8];
            *(float4*)&a[0] = *(const float4*)&As[buf][k][ty * 8];
            *(float4*)&a[4] = *(const float4*)&As[buf][k][ty * 8 + 4];
            *(float4*)&b[0] = *(const float4*)&Bs[buf][k][tx * 8];
            *(float4*)&b[4] = *(const float4*)&Bs[buf][k][tx * 8 + 4];
#pragma unroll
            for (int i = 0; i < 8; ++i)
#pragma unroll
                for (int j = 0; j < 8; ++j)
                    acc[i][j] += a[i] * b[j];
        }

        if (kt + 1 < KT) {
            const int nb = buf ^ 1;
#pragma unroll
            for (int i = 0; i < 4; ++i) {
                As[nb][lc + i][lr]      = ((const float*)&ra0)[i];
                As[nb][lc + i][lr + 64] = ((const float*)&ra1)[i];
                Bs[nb][lc + i][lr]      = ((const float*)&rb0)[i];
                Bs[nb][lc + i][lr + 64] = ((const float*)&rb1)[i];
            }
            buf = nb;
            __syncthreads();
        }
    }

    // epilogue: ehout = ehin + acc + bias
    float bv[8];
#pragma unroll
    for (int j = 0; j < 8; ++j) bv[j] = __ldg(&bias[nBase + tx * 8 + j]);

#pragma unroll
    for (int i = 0; i < 8; ++i) {
        const size_t row = (size_t)(mBase + ty * 8 + i) * D_N + nBase + tx * 8;
        float4 o0 = *(const float4*)(ehin + row);
        float4 o1 = *(const float4*)(ehin + row + 4);
        o0.x += acc[i][0] + bv[0];
        o0.y += acc[i][1] + bv[1];
        o0.z += acc[i][2] + bv[2];
        o0.w += acc[i][3] + bv[3];
        o1.x += acc[i][4] + bv[4];
        o1.y += acc[i][5] + bv[5];
        o1.z += acc[i][6] + bv[6];
        o1.w += acc[i][7] + bv[7];
        *(float4*)(ehout + row)     = o0;
        *(float4*)(ehout + row + 4) = o1;
    }
}

// ---------------------------------------------------------------------------
// node_hiddens[dest[e],:] += eh[e,:]   (final readout, no relu)
// ---------------------------------------------------------------------------
__global__ void k_scatter_final(const float* __restrict__ eh,
                                const int* __restrict__ dst,
                                float* __restrict__ outn) {
    int idx = blockIdx.x * blockDim.x + threadIdx.x;    // < E*D/4
    int e = idx >> 7;
    int c = (idx & 127) << 2;
    float4 v = *(const float4*)(eh + (size_t)e * D_N + c);
    int d = __ldg(&dst[e]);
    float* p = outn + (size_t)d * D_N + c;
    atomicAdd(p + 0, v.x);
    atomicAdd(p + 1, v.y);
    atomicAdd(p + 2, v.z);
    atomicAdd(p + 3, v.w);
}

// ---------------------------------------------------------------------------
extern "C" void kernel_launch(void* const* d_in, const int* in_sizes, int n_in,
                              void* d_out, int out_size) {
    const float* node_feats = (const float*)d_in[0];    // [V, D]
    const float* edge_feats = (const float*)d_in[1];    // [E, D]
    const float* Ws         = (const float*)d_in[2];    // [DEPTH, D, D]
    const float* bs         = (const float*)d_in[3];    // [DEPTH, D]
    const int*   edge_index = (const int*)  d_in[4];    // [2, E]
    const int*   rev_index  = (const int*)  d_in[5];    // [E]

    const int* src = edge_index;
    const int* dst = edge_index + E_N;

    float* out_nodes = (float*)d_out;                       // [V, D]
    float* eh_out    = (float*)d_out + (size_t)V_N * D_N;   // [E, D] final eh location

    float* eh_scratch = nullptr;
    cudaGetSymbolAddress((void**)&eh_scratch, g_eh);

    const int TPB = 256;
    const int edgeGrid = (E_N * (D_N / 4)) / TPB;           // 80000 blocks
    const int nmGrid = (V_N * (D_N / 4)) / TPB;             // 5000 blocks
    dim3 gemmGrid(D_N / BN, E_N / BM);                      // (4, 1250)

    // eh0 -> scratch
    k_init_eh<<<edgeGrid, TPB>>>(node_feats, edge_feats, src);

    // ping-pong: scratch -> out -> scratch -> out (DEPTH=3)
    float* bufs[2] = { eh_scratch, eh_out };
    for (int l = 0; l < DEPTH_N; ++l) {
        const float* ehin = bufs[l & 1];
        float*       eho  = bufs[(l + 1) & 1];
        k_zero_nm<<<nmGrid, TPB>>>();
        k_scatter_relu<<<edgeGrid, TPB>>>(ehin, dst);
        k_gemm_layer<<<gemmGrid, 256>>>(Ws + (size_t)l * D_N * D_N,
                                        bs + (size_t)l * D_N,
                                        ehin, eho, src, rev_index);
    }

    // node_hiddens = segment_sum(eh_final, dest)
    k_zero_ptr<<<nmGrid, TPB>>>((float4*)out_nodes, V_N * D_N / 4);
    k_scatter_final<<<edgeGrid, TPB>>>(eh_out, dst, out_nodes);
}

// round 4
// speedup vs baseline: 1.1311x; 1.1311x over previous
#include <cuda_runtime.h>
#include <cstdint>

// ChempropBlock: V=10000 nodes, E=160000 edges, D=512, DEPTH=3
// out = [node_hiddens (V*D) | eh (E*D)] fp32
//
// Per layer l:
//   nm         = segment_sum(relu(eh), dest)                      (atomic scatter)
//   ehout[m,:] = ehin[m,:] + (nm[src[m],:] - relu(ehin[rev[m],:])) @ W[l]^T + b[l]
// GEMM: mma.sync m16n8k8 tf32 with 3-term hi/lo split (fp32-accurate):
//   D += Ahi*Bhi + Alo*Bhi + Ahi*Blo    (hi = top-10 mantissa bits, exact tf32)
// Final: node_hiddens = segment_sum(eh, dest)

#define V_N 10000
#define E_N 160000
#define D_N 512
#define DEPTH_N 3

#define TM 128
#define TN 128
#define KC 32
#define NCHUNK (D_N / KC)     // 16

// Scratch (device globals: allocation APIs are banned)
__device__ float g_nm[(size_t)V_N * D_N];       // node messages, 20.5 MB
__device__ float g_eh[(size_t)E_N * D_N];       // ping-pong eh buffer, 327 MB

__device__ __forceinline__ float4 relu4(float4 v) {
    v.x = fmaxf(v.x, 0.f); v.y = fmaxf(v.y, 0.f);
    v.z = fmaxf(v.z, 0.f); v.w = fmaxf(v.w, 0.f);
    return v;
}
__device__ __forceinline__ float hi_tf32(float x) {
    return __uint_as_float(__float_as_uint(x) & 0xFFFFE000u);
}

// m16n8k8 tf32 MMA, fp32 accumulate in place
__device__ __forceinline__ void mma_tf32(float* d, const float* a, const float* b) {
    asm volatile(
        "mma.sync.aligned.m16n8k8.row.col.f32.tf32.tf32.f32 "
        "{%0,%1,%2,%3}, {%4,%5,%6,%7}, {%8,%9}, {%0,%1,%2,%3};"
        : "+f"(d[0]), "+f"(d[1]), "+f"(d[2]), "+f"(d[3])
        : "r"(__float_as_uint(a[0])), "r"(__float_as_uint(a[1])),
          "r"(__float_as_uint(a[2])), "r"(__float_as_uint(a[3])),
          "r"(__float_as_uint(b[0])), "r"(__float_as_uint(b[1])));
}

// ---------------------------------------------------------------------------
// misc small kernels (unchanged from passing R2 version)
// ---------------------------------------------------------------------------
__global__ void k_zero_nm() {
    int i = blockIdx.x * blockDim.x + threadIdx.x;
    ((float4*)g_nm)[i] = make_float4(0.f, 0.f, 0.f, 0.f);
}
__global__ void k_zero_ptr(float4* __restrict__ p, int n4) {
    int i = blockIdx.x * blockDim.x + threadIdx.x;
    if (i < n4) p[i] = make_float4(0.f, 0.f, 0.f, 0.f);
}
__global__ void k_init_eh(const float* __restrict__ nf,
                          const float* __restrict__ ef,
                          const int* __restrict__ src) {
    int idx = blockIdx.x * blockDim.x + threadIdx.x;
    int e = idx >> 7;
    int c = (idx & 127) << 2;
    int s = __ldg(&src[e]);
    const float4 a = *(const float4*)(nf + (size_t)s * D_N + c);
    const float4 b = *(const float4*)(ef + (size_t)e * D_N + c);
    float4 r; r.x = a.x + b.x; r.y = a.y + b.y; r.z = a.z + b.z; r.w = a.w + b.w;
    *(float4*)(g_eh + (size_t)e * D_N + c) = r;
}
__global__ void k_scatter_relu(const float* __restrict__ ehin,
                               const int* __restrict__ dst) {
    int idx = blockIdx.x * blockDim.x + threadIdx.x;
    int e = idx >> 7;
    int c = (idx & 127) << 2;
    float4 v = relu4(*(const float4*)(ehin + (size_t)e * D_N + c));
    int d = __ldg(&dst[e]);
    float* p = g_nm + (size_t)d * D_N + c;
    atomicAdd(p + 0, v.x); atomicAdd(p + 1, v.y);
    atomicAdd(p + 2, v.z); atomicAdd(p + 3, v.w);
}
__global__ void k_scatter_final(const float* __restrict__ eh,
                                const int* __restrict__ dst,
                                float* __restrict__ outn) {
    int idx = blockIdx.x * blockDim.x + threadIdx.x;
    int e = idx >> 7;
    int c = (idx & 127) << 2;
    float4 v = *(const float4*)(eh + (size_t)e * D_N + c);
    int d = __ldg(&dst[e]);
    float* p = outn + (size_t)d * D_N + c;
    atomicAdd(p + 0, v.x); atomicAdd(p + 1, v.y);
    atomicAdd(p + 2, v.z); atomicAdd(p + 3, v.w);
}

// ---------------------------------------------------------------------------
// TF32 mma.sync layer GEMM, fragment-permuted smem staging.
//
// smem layout (floats), double-buffered per K-chunk:
//   s_src[128], s_rev[128] (as ints, 1024 B)
//   FA[s]: [k8(4)][rb(8)][lane(32)][reg(4)]  = 4096 floats (16 KB)
//   FB[s]: [k8(4)][nb8(16)][lane(32)][reg(2)] = 4096 floats (16 KB)
// total = 1024 + 2*32768 B = 66560 B dynamic smem
//
// Fragment semantics (m16n8k8):
//   A reg r of lane l -> A[rb*16 + (r&1)*8 + l/4][k8*8 + (r>>1)*4 + l%4]
//   B reg r of lane l -> W [nb8*8 + l/4]        [k8*8 + r*4 + l%4]
//   C reg r of lane l -> D[row=l/4 + (r>=2)*8][col=2*(l%4) + (r&1)]
// ---------------------------------------------------------------------------
#define FA_OFF(s) (256 + (s) * 8192)         // float index
#define FB_OFF(s) (FA_OFF(s) + 4096)
#define SMEM_FLOATS (256 + 2 * 8192)         // 16640 floats = 66560 B

__global__ void __launch_bounds__(256, 2)
k_gemm_mma(const float* __restrict__ W,
           const float* __restrict__ bias,
           const float* __restrict__ ehin,
           float* __restrict__ ehout,
           const int* __restrict__ src,
           const int* __restrict__ rev) {
    extern __shared__ float smemf[];
    int* s_src = (int*)smemf;          // [128]
    int* s_rev = (int*)smemf + 128;    // [128]

    const int tid = threadIdx.x;
    const int wid = tid >> 5;
    const int lid = tid & 31;
    const int mBase = blockIdx.y * TM;
    const int nBase = blockIdx.x * TN;

    if (tid < TM) {
        s_src[tid] = __ldg(&src[mBase + tid]);
        s_rev[tid] = __ldg(&rev[mBase + tid]);
    }
    __syncthreads();

    // ---- staging: chunk c -> buffer s (fragment-permuted f32) ----
    const int st_row  = tid >> 1;        // 0..127 (A row / B row)
    const int st_half = (tid & 1) * 16;  // k offset base within chunk
    const float* Wp = W + (size_t)nBase * D_N;

    auto stage = [&](int c, int s) {
        const int kof = c * KC;
        float* FA = smemf + FA_OFF(s);
        float* FB = smemf + FB_OFF(s);
        const float* nrow = g_nm + (size_t)s_src[st_row] * D_N + kof;
        const float* hrow = ehin + (size_t)s_rev[st_row] * D_N + kof;
        const int rr = st_row & 15, rb = st_row >> 4;
        const int laneA = (rr & 7) * 4;
#pragma unroll
        for (int q = 0; q < 4; ++q) {
            const int af = st_half + q * 4;
            const float4 n4 = *(const float4*)(nrow + af);
            const float4 h4 = relu4(*(const float4*)(hrow + af));
            const int k8 = af >> 3;
            const int reg = (rr >> 3) + (((af >> 2) & 1) << 1);
            float* b = FA + ((k8 * 8 + rb) * 32 + laneA) * 4 + reg;
            b[0]  = n4.x - h4.x;
            b[4]  = n4.y - h4.y;
            b[8]  = n4.z - h4.z;
            b[12] = n4.w - h4.w;
        }
        const float* wrow = Wp + (size_t)st_row * D_N + kof;
        const int nb8 = st_row >> 3;
        const int laneB = (st_row & 7) * 4;
#pragma unroll
        for (int q = 0; q < 4; ++q) {
            const int af = st_half + q * 4;
            const float4 w4 = *(const float4*)(wrow + af);
            const int k8 = af >> 3;
            const int reg = (af >> 2) & 1;
            float* b = FB + ((k8 * 16 + nb8) * 32 + laneB) * 2 + reg;
            b[0] = w4.x; b[2] = w4.y; b[4] = w4.z; b[6] = w4.w;
        }
    };

    // ---- warp tiles: 2 (M) x 4 (N) of 64x32 ----
    const int wm = (wid >> 2) * 64;     // 0 or 64
    const int wn = (wid & 3) * 32;      // 0,32,64,96

    float acc[4][4][4];
#pragma unroll
    for (int i = 0; i < 4; ++i)
#pragma unroll
        for (int j = 0; j < 4; ++j)
#pragma unroll
            for (int k = 0; k < 4; ++k) acc[i][j][k] = 0.f;

    stage(0, 0);
    __syncthreads();

    for (int c = 0; c < NCHUNK; ++c) {
        if (c + 1 < NCHUNK) stage(c + 1, (c + 1) & 1);

        const float* FA = smemf + FA_OFF(c & 1);
        const float* FB = smemf + FB_OFF(c & 1);
#pragma unroll
        for (int k8 = 0; k8 < 4; ++k8) {
            float bhi[4][2], blo[4][2];
#pragma unroll
            for (int nb = 0; nb < 4; ++nb) {
                const float2 b2 = *(const float2*)
                    (FB + ((k8 * 16 + (wn >> 3) + nb) * 32 + lid) * 2);
                bhi[nb][0] = hi_tf32(b2.x); blo[nb][0] = b2.x - bhi[nb][0];
                bhi[nb][1] = hi_tf32(b2.y); blo[nb][1] = b2.y - bhi[nb][1];
            }
#pragma unroll
            for (int rb = 0; rb < 4; ++rb) {
                const float4 a4 = *(const float4*)
                    (FA + ((k8 * 8 + (wm >> 4) + rb) * 32 + lid) * 4);
                float ahi[4], alo[4];
                ahi[0] = hi_tf32(a4.x); alo[0] = a4.x - ahi[0];
                ahi[1] = hi_tf32(a4.y); alo[1] = a4.y - ahi[1];
                ahi[2] = hi_tf32(a4.z); alo[2] = a4.z - ahi[2];
                ahi[3] = hi_tf32(a4.w); alo[3] = a4.w - ahi[3];
#pragma unroll
                for (int nb = 0; nb < 4; ++nb) {
                    mma_tf32(acc[rb][nb], ahi, bhi[nb]);
                    mma_tf32(acc[rb][nb], alo, bhi[nb]);
                    mma_tf32(acc[rb][nb], ahi, blo[nb]);
                }
            }
        }
        __syncthreads();
    }

    // ---- epilogue: ehout = ehin + acc + bias ----
#pragma unroll
    for (int rb = 0; rb < 4; ++rb) {
#pragma unroll
        for (int half = 0; half < 2; ++half) {
            const int m = mBase + wm + rb * 16 + half * 8 + (lid >> 2);
            const float* ein = ehin + (size_t)m * D_N + nBase;
            float* eout = ehout + (size_t)m * D_N + nBase;
#pragma unroll
            for (int nb = 0; nb < 4; ++nb) {
                const int cc = wn + nb * 8 + 2 * (lid & 3);
                float2 e = *(const float2*)(ein + cc);
                e.x += acc[rb][nb][half * 2 + 0] + __ldg(&bias[nBase + cc]);
                e.y += acc[rb][nb][half * 2 + 1] + __ldg(&bias[nBase + cc + 1]);
                *(float2*)(eout + cc) = e;
            }
        }
    }
}

// ---------------------------------------------------------------------------
extern "C" void kernel_launch(void* const* d_in, const int* in_sizes, int n_in,
                              void* d_out, int out_size) {
    const float* node_feats = (const float*)d_in[0];
    const float* edge_feats = (const float*)d_in[1];
    const float* Ws         = (const float*)d_in[2];
    const float* bs         = (const float*)d_in[3];
    const int*   edge_index = (const int*)  d_in[4];
    const int*   rev_index  = (const int*)  d_in[5];

    const int* src = edge_index;
    const int* dst = edge_index + E_N;

    float* out_nodes = (float*)d_out;
    float* eh_out    = (float*)d_out + (size_t)V_N * D_N;

    float* eh_scratch = nullptr;
    cudaGetSymbolAddress((void**)&eh_scratch, g_eh);

    const int smem_bytes = SMEM_FLOATS * 4;   // 66560
    cudaFuncSetAttribute(k_gemm_mma,
                         cudaFuncAttributeMaxDynamicSharedMemorySize, smem_bytes);

    const int TPB = 256;
    const int edgeGrid = (E_N * (D_N / 4)) / TPB;   // 80000
    const int nmGrid   = (V_N * (D_N / 4)) / TPB;   // 5000
    dim3 gemmGrid(D_N / TN, E_N / TM);              // (4, 1250)

    k_init_eh<<<edgeGrid, TPB>>>(node_feats, edge_feats, src);

    float* bufs[2] = { eh_scratch, eh_out };
    for (int l = 0; l < DEPTH_N; ++l) {
        const float* ehin = bufs[l & 1];
        float*       eho  = bufs[(l + 1) & 1];
        k_zero_nm<<<nmGrid, TPB>>>();
        k_scatter_relu<<<edgeGrid, TPB>>>(ehin, dst);
        k_gemm_mma<<<gemmGrid, TPB, smem_bytes>>>(Ws + (size_t)l * D_N * D_N,
                                                  bs + (size_t)l * D_N,
                                                  ehin, eho, src, rev_index);
    }

    k_zero_ptr<<<nmGrid, TPB>>>((float4*)out_nodes, V_N * D_N / 4);
    k_scatter_final<<<edgeGrid, TPB>>>(eh_out, dst, out_nodes);
}

// round 6
// speedup vs baseline: 1.2483x; 1.1036x over previous
#include <cuda_runtime.h>
#include <cstdint>

// ChempropBlock: V=10000 nodes, E=160000 edges, D=512, DEPTH=3
// out = [node_hiddens (V*D) | eh (E*D)] fp32
//
// Per layer l:
//   nm_cur = segment_sum(relu(eh), dest)   (produced by previous epilogue / init)
//   ehout  = ehin + (nm_cur[src] - relu(ehin[rev])) @ W[l]^T + b[l]
//   epilogue scatters relu(ehout) into nm_next (or plain ehout into out_nodes
//   on the last layer) -> standalone scatter passes eliminated.
// GEMM: mma.sync m16n8k8 tf32, 3-term hi/lo split (D += AhiBhi + AloBhi + AhiBlo).
// Pipeline per K-chunk: A gathers for c+1 prefetched to REGISTERS, W for c+1
// staged from L2 (both overlap the chunk-c MMA loop); A committed to smem after.

#define V_N 10000
#define E_N 160000
#define D_N 512
#define DEPTH_N 3

#define TM 128
#define TN 128
#define KC 32
#define NCHUNK (D_N / KC)     // 16

// Scratch (device globals: allocation APIs are banned)
__device__ float g_nm0[(size_t)V_N * D_N];
__device__ float g_nm1[(size_t)V_N * D_N];
__device__ float g_eh[(size_t)E_N * D_N];

__device__ __forceinline__ float4 relu4(float4 v) {
    v.x = fmaxf(v.x, 0.f); v.y = fmaxf(v.y, 0.f);
    v.z = fmaxf(v.z, 0.f); v.w = fmaxf(v.w, 0.f);
    return v;
}
__device__ __forceinline__ float hi_tf32(float x) {
    return __uint_as_float(__float_as_uint(x) & 0xFFFFE000u);
}

__device__ __forceinline__ void mma_tf32(float* d, const float* a, const float* b) {
    asm volatile(
        "mma.sync.aligned.m16n8k8.row.col.f32.tf32.tf32.f32 "
        "{%0,%1,%2,%3}, {%4,%5,%6,%7}, {%8,%9}, {%0,%1,%2,%3};"
        : "+f"(d[0]), "+f"(d[1]), "+f"(d[2]), "+f"(d[3])
        : "r"(__float_as_uint(a[0])), "r"(__float_as_uint(a[1])),
          "r"(__float_as_uint(a[2])), "r"(__float_as_uint(a[3])),
          "r"(__float_as_uint(b[0])), "r"(__float_as_uint(b[1])));
}

// ---------------------------------------------------------------------------
__global__ void k_zero_ptr(float4* __restrict__ p, int n4) {
    int i = blockIdx.x * blockDim.x + threadIdx.x;
    if (i < n4) p[i] = make_float4(0.f, 0.f, 0.f, 0.f);
}

// eh0 = nf[src] + ef ; relu-scatter eh0 into nm (fused first message pass)
__global__ void k_init_eh_scatter(const float* __restrict__ nf,
                                  const float* __restrict__ ef,
                                  const int* __restrict__ src,
                                  const int* __restrict__ dst,
                                  float* __restrict__ nm) {
    int idx = blockIdx.x * blockDim.x + threadIdx.x;   // < E*D/4
    int e = idx >> 7;
    int c = (idx & 127) << 2;
    int s = __ldg(&src[e]);
    const float4 a = *(const float4*)(nf + (size_t)s * D_N + c);
    const float4 b = *(const float4*)(ef + (size_t)e * D_N + c);
    float4 r; r.x = a.x + b.x; r.y = a.y + b.y; r.z = a.z + b.z; r.w = a.w + b.w;
    *(float4*)(g_eh + (size_t)e * D_N + c) = r;
    int d = __ldg(&dst[e]);
    float* p = nm + (size_t)d * D_N + c;
    atomicAdd(p + 0, fmaxf(r.x, 0.f));
    atomicAdd(p + 1, fmaxf(r.y, 0.f));
    atomicAdd(p + 2, fmaxf(r.z, 0.f));
    atomicAdd(p + 3, fmaxf(r.w, 0.f));
}

// ---------------------------------------------------------------------------
// smem layout (float indices):
//   [0..383]   s_src / s_rev / s_dst (ints, 128 each); pad to 512
//   FA(s) = 512  + s*4096 : [k8(4)][rb(8)][lane(32)][reg(4)]  per stage
//   FB(s) = 8704 + s*4096 : [k8(4)][nb8(16)][lane(32)][reg(2)] per stage
// total 16896 floats = 67584 B -> 2 CTA/SM
//
// Fragment semantics (m16n8k8):
//   A reg r of lane l -> A[rb*16 + (r&1)*8 + l/4][k8*8 + (r>>1)*4 + l%4]
//   B reg r of lane l -> W [nb8*8 + l/4]        [k8*8 + r*4 + l%4]
//   C reg r of lane l -> D[row=l/4 + (r>=2)*8][col=2*(l%4) + (r&1)]
// ---------------------------------------------------------------------------
#define FA_OFF(s) (512 + (s) * 4096)
#define FB_OFF(s) (8704 + (s) * 4096)
#define SMEM_FLOATS (512 + 4 * 4096)     // 16896 -> 67584 B

__global__ void __launch_bounds__(256, 2)
k_gemm_mma(const float* __restrict__ W,
           const float* __restrict__ bias,
           const float* __restrict__ nm,
           const float* __restrict__ ehin,
           float* __restrict__ ehout,
           const int* __restrict__ src,
           const int* __restrict__ rev,
           const int* __restrict__ dst,
           float* __restrict__ scat,      // nm_next (relu) or out_nodes (plain)
           int do_relu) {
    extern __shared__ float smemf[];
    int* s_src = (int*)smemf;
    int* s_rev = (int*)smemf + 128;
    int* s_dst = (int*)smemf + 256;

    const int tid = threadIdx.x;
    const int wid = tid >> 5;
    const int lid = tid & 31;
    const int mBase = blockIdx.y * TM;
    const int nBase = blockIdx.x * TN;

    if (tid < TM) {
        s_src[tid] = __ldg(&src[mBase + tid]);
        s_rev[tid] = __ldg(&rev[mBase + tid]);
        s_dst[tid] = __ldg(&dst[mBase + tid]);
    }
    __syncthreads();

    // per-thread staging coordinates (2 threads per row, 16 floats each)
    const int st_row  = tid >> 1;          // 0..127
    const int st_half = (tid & 1) * 16;    // k offset within 32-chunk
    const int rr  = st_row & 15, rb = st_row >> 4;
    const int laneA = (rr & 7) * 4;
    const int nb8 = st_row >> 3;
    const int laneB = (st_row & 7) * 4;

    const size_t nm_off = (size_t)s_src[st_row] * D_N;
    const size_t eh_off = (size_t)s_rev[st_row] * D_N;
    const float* wrow = W + (size_t)(nBase + st_row) * D_N;

    // A prefetch to registers; commit splits into fragment layout
    float4 pn[4], ph[4];
    auto prefetchA = [&](int c) {
        const int kof = c * KC + st_half;
#pragma unroll
        for (int q = 0; q < 4; ++q) {
            pn[q] = *(const float4*)(nm + nm_off + kof + q * 4);
            ph[q] = *(const float4*)(ehin + eh_off + kof + q * 4);
        }
    };
    auto commitA = [&](int s) {
        float* FA = smemf + FA_OFF(s);
#pragma unroll
        for (int q = 0; q < 4; ++q) {
            const int af = st_half + q * 4;
            const float4 h4 = relu4(ph[q]);
            const int k8 = af >> 3;
            const int reg = (rr >> 3) + (((af >> 2) & 1) << 1);
            float* b = FA + ((k8 * 8 + rb) * 32 + laneA) * 4 + reg;
            b[0]  = pn[q].x - h4.x;
            b[4]  = pn[q].y - h4.y;
            b[8]  = pn[q].z - h4.z;
            b[12] = pn[q].w - h4.w;
        }
    };
    // W staged straight through (L2-resident; latency overlapped by A gathers)
    auto stageW = [&](int c, int s) {
        float* FB = smemf + FB_OFF(s);
#pragma unroll
        for (int q = 0; q < 4; ++q) {
            const int af = st_half + q * 4;                // 0..31
            const float4 w4 = *(const float4*)(wrow + c * KC + af);
            const int k8 = af >> 3;                        // 0..3
            const int reg = (af >> 2) & 1;
            float* b = FB + ((k8 * 16 + nb8) * 32 + laneB) * 2 + reg;
            b[0] = w4.x; b[2] = w4.y; b[4] = w4.z; b[6] = w4.w;
        }
    };

    // ---- warp tiles: 2 (M) x 4 (N) of 64x32 ----
    const int wm = (wid >> 2) * 64;
    const int wn = (wid & 3) * 32;

    float acc[4][4][4];
#pragma unroll
    for (int i = 0; i < 4; ++i)
#pragma unroll
        for (int j = 0; j < 4; ++j)
#pragma unroll
            for (int k = 0; k < 4; ++k) acc[i][j][k] = 0.f;

    prefetchA(0);
    stageW(0, 0);
    commitA(0);
    __syncthreads();

    for (int c = 0; c < NCHUNK; ++c) {
        if (c + 1 < NCHUNK) {
            prefetchA(c + 1);          // random-gather LDGs in flight
            stageW(c + 1, (c + 1) & 1);
        }

        const float* FA = smemf + FA_OFF(c & 1);
        const float* FB = smemf + FB_OFF(c & 1);
#pragma unroll
        for (int k8 = 0; k8 < 4; ++k8) {
            float bhi[4][2], blo[4][2];
#pragma unroll
            for (int nb = 0; nb < 4; ++nb) {
                const float2 b2 = *(const float2*)
                    (FB + ((k8 * 16 + (wn >> 3) + nb) * 32 + lid) * 2);
                bhi[nb][0] = hi_tf32(b2.x); blo[nb][0] = b2.x - bhi[nb][0];
                bhi[nb][1] = hi_tf32(b2.y); blo[nb][1] = b2.y - bhi[nb][1];
            }
#pragma unroll
            for (int rbi = 0; rbi < 4; ++rbi) {
                const float4 a4 = *(const float4*)
                    (FA + ((k8 * 8 + (wm >> 4) + rbi) * 32 + lid) * 4);
                float ahi[4], alo[4];
                ahi[0] = hi_tf32(a4.x); alo[0] = a4.x - ahi[0];
                ahi[1] = hi_tf32(a4.y); alo[1] = a4.y - ahi[1];
                ahi[2] = hi_tf32(a4.z); alo[2] = a4.z - ahi[2];
                ahi[3] = hi_tf32(a4.w); alo[3] = a4.w - ahi[3];
#pragma unroll
                for (int nb = 0; nb < 4; ++nb) {
                    mma_tf32(acc[rbi][nb], ahi, bhi[nb]);
                    mma_tf32(acc[rbi][nb], alo, bhi[nb]);
                    mma_tf32(acc[rbi][nb], ahi, blo[nb]);
                }
            }
        }

        if (c + 1 < NCHUNK) commitA((c + 1) & 1);
        __syncthreads();
    }

    // ---- epilogue: ehout = ehin + acc + bias; fused scatter ----
#pragma unroll
    for (int rbi = 0; rbi < 4; ++rbi) {
#pragma unroll
        for (int half = 0; half < 2; ++half) {
            const int mi = wm + rbi * 16 + half * 8 + (lid >> 2);
            const int m = mBase + mi;
            const int d = s_dst[mi];
            const float* ein = ehin + (size_t)m * D_N + nBase;
            float* eout = ehout + (size_t)m * D_N + nBase;
            float* srow = scat + (size_t)d * D_N + nBase;
#pragma unroll
            for (int nb = 0; nb < 4; ++nb) {
                const int cc = wn + nb * 8 + 2 * (lid & 3);
                float2 e = *(const float2*)(ein + cc);
                e.x += acc[rbi][nb][half * 2 + 0] + __ldg(&bias[nBase + cc]);
                e.y += acc[rbi][nb][half * 2 + 1] + __ldg(&bias[nBase + cc + 1]);
                *(float2*)(eout + cc) = e;
                if (do_relu) {
                    atomicAdd(srow + cc,     fmaxf(e.x, 0.f));
                    atomicAdd(srow + cc + 1, fmaxf(e.y, 0.f));
                } else {
                    atomicAdd(srow + cc,     e.x);
                    atomicAdd(srow + cc + 1, e.y);
                }
            }
        }
    }
}

// ---------------------------------------------------------------------------
extern "C" void kernel_launch(void* const* d_in, const int* in_sizes, int n_in,
                              void* d_out, int out_size) {
    const float* node_feats = (const float*)d_in[0];
    const float* edge_feats = (const float*)d_in[1];
    const float* Ws         = (const float*)d_in[2];
    const float* bs         = (const float*)d_in[3];
    const int*   edge_index = (const int*)  d_in[4];
    const int*   rev_index  = (const int*)  d_in[5];

    const int* src = edge_index;
    const int* dst = edge_index + E_N;

    float* out_nodes = (float*)d_out;
    float* eh_out    = (float*)d_out + (size_t)V_N * D_N;

    float *eh_scratch = nullptr, *nm0 = nullptr, *nm1 = nullptr;
    cudaGetSymbolAddress((void**)&eh_scratch, g_eh);
    cudaGetSymbolAddress((void**)&nm0, g_nm0);
    cudaGetSymbolAddress((void**)&nm1, g_nm1);

    const int smem_bytes = SMEM_FLOATS * 4;    // 67584
    cudaFuncSetAttribute(k_gemm_mma,
                         cudaFuncAttributeMaxDynamicSharedMemorySize, smem_bytes);

    const int TPB = 256;
    const int edgeGrid = (E_N * (D_N / 4)) / TPB;   // 80000
    const int nmGrid   = (V_N * (D_N / 4)) / TPB;   // 5000
    dim3 gemmGrid(D_N / TN, E_N / TM);              // (4, 1250)

    k_zero_ptr<<<nmGrid, TPB>>>((float4*)nm0, V_N * D_N / 4);
    k_init_eh_scatter<<<edgeGrid, TPB>>>(node_feats, edge_feats, src, dst, nm0);

    float* ehbufs[2] = { eh_scratch, eh_out };
    float* nmbufs[2] = { nm0, nm1 };
    for (int l = 0; l < DEPTH_N; ++l) {
        const float* ehin = ehbufs[l & 1];
        float*       eho  = ehbufs[(l + 1) & 1];
        const float* nmc  = nmbufs[l & 1];
        float*       scat;
        int          do_relu;
        if (l + 1 < DEPTH_N) {
            scat = nmbufs[(l + 1) & 1];
            do_relu = 1;
            k_zero_ptr<<<nmGrid, TPB>>>((float4*)scat, V_N * D_N / 4);
        } else {
            scat = out_nodes;
            do_relu = 0;
            k_zero_ptr<<<nmGrid, TPB>>>((float4*)out_nodes, V_N * D_N / 4);
        }
        k_gemm_mma<<<gemmGrid, TPB, smem_bytes>>>(
            Ws + (size_t)l * D_N * D_N, bs + (size_t)l * D_N,
            nmc, ehin, eho, src, rev_index, dst, scat, do_relu);
    }
}

// round 7
// speedup vs baseline: 1.5316x; 1.2270x over previous
#include <cuda_runtime.h>
#include <cstdint>

// ChempropBlock: V=10000 nodes, E=160000 edges, D=512, DEPTH=3
// out = [node_hiddens (V*D) | eh (E*D)] fp32
//
// Per layer l:
//   nm_cur = segment_sum(relu(eh), dest)   (produced by previous epilogue / init)
//   ehout  = ehin + (nm_cur[src] - relu(ehin[rev])) @ W[l]^T + b[l]
//   epilogue scatters relu(ehout) into nm_next (plain into out_nodes last layer).
// GEMM: mma.sync m16n8k8 tf32, 3-term hi/lo split (D += AhiBhi + AloBhi + AhiBlo).
// Data movement rebuilt for minimal L1 wavefronts:
//  - gathers: 8 threads/row -> warp LDG covers 4 full 128B rows (4 wf/instr)
//  - smem: swizzled row-major (granule (k>>2)^(row&7)); commits are STS.128,
//    fragment loads are conflict-free scalar LDS.32
//  - W staged with cp.async.cg (L2->smem, bypasses L1 + registers)

#define V_N 10000
#define E_N 160000
#define D_N 512
#define DEPTH_N 3

#define TM 128
#define TN 128
#define KC 32
#define NCHUNK (D_N / KC)     // 16

__device__ float g_nm0[(size_t)V_N * D_N];
__device__ float g_nm1[(size_t)V_N * D_N];
__device__ float g_eh[(size_t)E_N * D_N];

__device__ __forceinline__ float4 relu4(float4 v) {
    v.x = fmaxf(v.x, 0.f); v.y = fmaxf(v.y, 0.f);
    v.z = fmaxf(v.z, 0.f); v.w = fmaxf(v.w, 0.f);
    return v;
}
__device__ __forceinline__ float hi_tf32(float x) {
    return __uint_as_float(__float_as_uint(x) & 0xFFFFE000u);
}
__device__ __forceinline__ uint32_t smem_u32(const void* p) {
    uint32_t a;
    asm("{ .reg .u64 t; cvta.to.shared.u64 t, %1; cvt.u32.u64 %0, t; }"
        : "=r"(a) : "l"(p));
    return a;
}

__device__ __forceinline__ void mma_tf32(float* d, const float* a, const float* b) {
    asm volatile(
        "mma.sync.aligned.m16n8k8.row.col.f32.tf32.tf32.f32 "
        "{%0,%1,%2,%3}, {%4,%5,%6,%7}, {%8,%9}, {%0,%1,%2,%3};"
        : "+f"(d[0]), "+f"(d[1]), "+f"(d[2]), "+f"(d[3])
        : "r"(__float_as_uint(a[0])), "r"(__float_as_uint(a[1])),
          "r"(__float_as_uint(a[2])), "r"(__float_as_uint(a[3])),
          "r"(__float_as_uint(b[0])), "r"(__float_as_uint(b[1])));
}

#define CP_ASYNC_16(dst_u32, src_ptr) \
    asm volatile("cp.async.cg.shared.global [%0], [%1], 16;" \
                 :: "r"(dst_u32), "l"(src_ptr) : "memory")
#define CP_ASYNC_COMMIT() asm volatile("cp.async.commit_group;" ::: "memory")
#define CP_ASYNC_WAIT0()  asm volatile("cp.async.wait_group 0;" ::: "memory")

// ---------------------------------------------------------------------------
__global__ void k_zero_ptr(float4* __restrict__ p, int n4) {
    int i = blockIdx.x * blockDim.x + threadIdx.x;
    if (i < n4) p[i] = make_float4(0.f, 0.f, 0.f, 0.f);
}

// eh0 = nf[src] + ef ; relu-scatter eh0 into nm
__global__ void k_init_eh_scatter(const float* __restrict__ nf,
                                  const float* __restrict__ ef,
                                  const int* __restrict__ src,
                                  const int* __restrict__ dst,
                                  float* __restrict__ nm) {
    int idx = blockIdx.x * blockDim.x + threadIdx.x;   // < E*D/4
    int e = idx >> 7;
    int c = (idx & 127) << 2;
    int s = __ldg(&src[e]);
    const float4 a = *(const float4*)(nf + (size_t)s * D_N + c);
    const float4 b = *(const float4*)(ef + (size_t)e * D_N + c);
    float4 r; r.x = a.x + b.x; r.y = a.y + b.y; r.z = a.z + b.z; r.w = a.w + b.w;
    *(float4*)(g_eh + (size_t)e * D_N + c) = r;
    int d = __ldg(&dst[e]);
    float* p = nm + (size_t)d * D_N + c;
    atomicAdd(p + 0, fmaxf(r.x, 0.f));
    atomicAdd(p + 1, fmaxf(r.y, 0.f));
    atomicAdd(p + 2, fmaxf(r.z, 0.f));
    atomicAdd(p + 3, fmaxf(r.w, 0.f));
}

// ---------------------------------------------------------------------------
// smem (float indices):
//   [0..383]  s_src / s_rev / s_dst (128 ints each), pad to 512
//   SA(s) = 512  + s*4096 : A tile, swizzled row-major, 128 rows x 32 floats
//   SB(s) = 8704 + s*4096 : W tile, same layout
// element (row, k) -> row*32 + ((k>>2) ^ (row & 7))*4 + (k & 3)
// total 16896 floats = 67584 B -> 2 CTA/SM
//
// Fragment semantics (m16n8k8, validated in R4/R6):
//   A reg r of lane l -> A[rb*16 + (r&1)*8 + l/4][k8*8 + (r>>1)*4 + l%4]
//   B reg r of lane l -> W [n8*8 + l/4]          [k8*8 + r*4 + l%4]
//   C reg r of lane l -> D[row=l/4 + (r>=2)*8][col=2*(l%4) + (r&1)]
// ---------------------------------------------------------------------------
#define SA_F(s) (512 + (s) * 4096)
#define SB_F(s) (8704 + (s) * 4096)
#define SMEM_FLOATS (512 + 4 * 4096)    // 16896 -> 67584 B

__global__ void __launch_bounds__(256, 2)
k_gemm_mma(const float* __restrict__ W,
           const float* __restrict__ bias,
           const float* __restrict__ nm,
           const float* __restrict__ ehin,
           float* __restrict__ ehout,
           const int* __restrict__ src,
           const int* __restrict__ rev,
           const int* __restrict__ dst,
           float* __restrict__ scat,
           int do_relu) {
    extern __shared__ float smemf[];
    int* s_src = (int*)smemf;
    int* s_rev = (int*)smemf + 128;
    int* s_dst = (int*)smemf + 256;

    const int tid = threadIdx.x;
    const int wid = tid >> 5;
    const int lid = tid & 31;
    const int mBase = blockIdx.y * TM;
    const int nBase = blockIdx.x * TN;

    if (tid < TM) {
        s_src[tid] = __ldg(&src[mBase + tid]);
        s_rev[tid] = __ldg(&rev[mBase + tid]);
        s_dst[tid] = __ldg(&dst[mBase + tid]);
    }
    __syncthreads();

    // ---- staging coordinates: 8 threads per row, 16B (4 floats) each ----
    const int st_r0 = tid >> 3;                  // base row 0..31 (+32*pass)
    const int st_kp = tid & 7;                   // 16B granule within 128B
    const int sw_g  = st_kp ^ (st_r0 & 7);       // swizzled granule (row&7 inv. to pass)

    uint32_t nmOff[4], ehOff[4];
#pragma unroll
    for (int p = 0; p < 4; ++p) {
        const int row = st_r0 + 32 * p;
        nmOff[p] = (uint32_t)s_src[row] * D_N + st_kp * 4;
        ehOff[p] = (uint32_t)s_rev[row] * D_N + st_kp * 4;
    }
    const float* wbase = W + (size_t)nBase * D_N + st_kp * 4;
    const uint32_t sb = smem_u32(smemf);

    // A prefetch to registers
    float4 pn[4], ph[4];
    auto prefetchA = [&](int c) {
        const int kof = c * KC;
#pragma unroll
        for (int p = 0; p < 4; ++p) {
            pn[p] = *(const float4*)(nm + nmOff[p] + kof);
            ph[p] = *(const float4*)(ehin + ehOff[p] + kof);
        }
    };
    // commit em = pn - relu(ph) as STS.128 into swizzled row-major SA
    auto commitA = [&](int s) {
        char* SA = (char*)(smemf + SA_F(s));
#pragma unroll
        for (int p = 0; p < 4; ++p) {
            const float4 h4 = relu4(ph[p]);
            float4 em;
            em.x = pn[p].x - h4.x; em.y = pn[p].y - h4.y;
            em.z = pn[p].z - h4.z; em.w = pn[p].w - h4.w;
            *(float4*)(SA + (st_r0 + 32 * p) * 128 + sw_g * 16) = em;
        }
    };
    // W staged via cp.async.cg (no registers, no STS pipeline)
    auto stageW = [&](int c, int s) {
        const uint32_t dbase = sb + SB_F(s) * 4 + sw_g * 16;
#pragma unroll
        for (int p = 0; p < 4; ++p) {
            const int row = st_r0 + 32 * p;
            CP_ASYNC_16(dbase + row * 128, wbase + (size_t)row * D_N + c * KC);
        }
        CP_ASYNC_COMMIT();
    };

    // ---- warp tiles: 2 (M) x 4 (N) of 64x32 ----
    const int wm = (wid >> 2) * 64;
    const int wn = (wid & 3) * 32;
    const int lr4 = lid >> 2;       // 0..7
    const int lm4 = lid & 3;        // 0..3

    float acc[4][4][4];
#pragma unroll
    for (int i = 0; i < 4; ++i)
#pragma unroll
        for (int j = 0; j < 4; ++j)
#pragma unroll
            for (int k = 0; k < 4; ++k) acc[i][j][k] = 0.f;

    prefetchA(0);
    stageW(0, 0);
    commitA(0);
    CP_ASYNC_WAIT0();
    __syncthreads();

    for (int c = 0; c < NCHUNK; ++c) {
        if (c + 1 < NCHUNK) {
            prefetchA(c + 1);               // random-gather LDGs in flight
            stageW(c + 1, (c + 1) & 1);     // L2->smem async
        }

        const float* SA = smemf + SA_F(c & 1) + lm4;
        const float* SB = smemf + SB_F(c & 1) + lm4;
#pragma unroll
        for (int k8 = 0; k8 < 4; ++k8) {
            const int g0 = (k8 * 2) ^ lr4;
            const int g1 = g0 ^ 1;
            float bhi[4][2], blo[4][2];
#pragma unroll
            for (int nb = 0; nb < 4; ++nb) {
                const float* bp = SB + (wn + nb * 8 + lr4) * 32;
                const float b0 = bp[g0 * 4];
                const float b1 = bp[g1 * 4];
                bhi[nb][0] = hi_tf32(b0); blo[nb][0] = b0 - bhi[nb][0];
                bhi[nb][1] = hi_tf32(b1); blo[nb][1] = b1 - bhi[nb][1];
            }
#pragma unroll
            for (int rbi = 0; rbi < 4; ++rbi) {
                const float* ap = SA + (wm + rbi * 16 + lr4) * 32;
                const float a0 = ap[g0 * 4];          // row+0, k+0
                const float a1 = ap[256 + g0 * 4];    // row+8, k+0
                const float a2 = ap[g1 * 4];          // row+0, k+4
                const float a3 = ap[256 + g1 * 4];    // row+8, k+4
                float ahi[4], alo[4];
                ahi[0] = hi_tf32(a0); alo[0] = a0 - ahi[0];
                ahi[1] = hi_tf32(a1); alo[1] = a1 - ahi[1];
                ahi[2] = hi_tf32(a2); alo[2] = a2 - ahi[2];
                ahi[3] = hi_tf32(a3); alo[3] = a3 - ahi[3];
#pragma unroll
                for (int nb = 0; nb < 4; ++nb) {
                    mma_tf32(acc[rbi][nb], ahi, bhi[nb]);
                    mma_tf32(acc[rbi][nb], alo, bhi[nb]);
                    mma_tf32(acc[rbi][nb], ahi, blo[nb]);
                }
            }
        }

        if (c + 1 < NCHUNK) {
            commitA((c + 1) & 1);
            CP_ASYNC_WAIT0();
        }
        __syncthreads();
    }

    // ---- epilogue: ehout = ehin + acc + bias; fused scatter ----
#pragma unroll
    for (int rbi = 0; rbi < 4; ++rbi) {
#pragma unroll
        for (int half = 0; half < 2; ++half) {
            const int mi = wm + rbi * 16 + half * 8 + lr4;
            const int m = mBase + mi;
            const int d = s_dst[mi];
            const float* ein = ehin + (size_t)m * D_N + nBase;
            float* eout = ehout + (size_t)m * D_N + nBase;
            float* srow = scat + (size_t)d * D_N + nBase;
#pragma unroll
            for (int nb = 0; nb < 4; ++nb) {
                const int cc = wn + nb * 8 + 2 * lm4;
                float2 e = *(const float2*)(ein + cc);
                e.x += acc[rbi][nb][half * 2 + 0] + __ldg(&bias[nBase + cc]);
                e.y += acc[rbi][nb][half * 2 + 1] + __ldg(&bias[nBase + cc + 1]);
                *(float2*)(eout + cc) = e;
                if (do_relu) {
                    atomicAdd(srow + cc,     fmaxf(e.x, 0.f));
                    atomicAdd(srow + cc + 1, fmaxf(e.y, 0.f));
                } else {
                    atomicAdd(srow + cc,     e.x);
                    atomicAdd(srow + cc + 1, e.y);
                }
            }
        }
    }
}

// ---------------------------------------------------------------------------
extern "C" void kernel_launch(void* const* d_in, const int* in_sizes, int n_in,
                              void* d_out, int out_size) {
    const float* node_feats = (const float*)d_in[0];
    const float* edge_feats = (const float*)d_in[1];
    const float* Ws         = (const float*)d_in[2];
    const float* bs         = (const float*)d_in[3];
    const int*   edge_index = (const int*)  d_in[4];
    const int*   rev_index  = (const int*)  d_in[5];

    const int* src = edge_index;
    const int* dst = edge_index + E_N;

    float* out_nodes = (float*)d_out;
    float* eh_out    = (float*)d_out + (size_t)V_N * D_N;

    float *eh_scratch = nullptr, *nm0 = nullptr, *nm1 = nullptr;
    cudaGetSymbolAddress((void**)&eh_scratch, g_eh);
    cudaGetSymbolAddress((void**)&nm0, g_nm0);
    cudaGetSymbolAddress((void**)&nm1, g_nm1);

    const int smem_bytes = SMEM_FLOATS * 4;    // 67584
    cudaFuncSetAttribute(k_gemm_mma,
                         cudaFuncAttributeMaxDynamicSharedMemorySize, smem_bytes);

    const int TPB = 256;
    const int edgeGrid = (E_N * (D_N / 4)) / TPB;   // 80000
    const int nmGrid   = (V_N * (D_N / 4)) / TPB;   // 5000
    dim3 gemmGrid(D_N / TN, E_N / TM);              // (4, 1250)

    k_zero_ptr<<<nmGrid, TPB>>>((float4*)nm0, V_N * D_N / 4);
    k_init_eh_scatter<<<edgeGrid, TPB>>>(node_feats, edge_feats, src, dst, nm0);

    float* ehbufs[2] = { eh_scratch, eh_out };
    float* nmbufs[2] = { nm0, nm1 };
    for (int l = 0; l < DEPTH_N; ++l) {
        const float* ehin = ehbufs[l & 1];
        float*       eho  = ehbufs[(l + 1) & 1];
        const float* nmc  = nmbufs[l & 1];
        float*       scat;
        int          do_relu;
        if (l + 1 < DEPTH_N) {
            scat = nmbufs[(l + 1) & 1];
            do_relu = 1;
            k_zero_ptr<<<nmGrid, TPB>>>((float4*)scat, V_N * D_N / 4);
        } else {
            scat = out_nodes;
            do_relu = 0;
            k_zero_ptr<<<nmGrid, TPB>>>((float4*)out_nodes, V_N * D_N / 4);
        }
        k_gemm_mma<<<gemmGrid, TPB, smem_bytes>>>(
            Ws + (size_t)l * D_N * D_N, bs + (size_t)l * D_N,
            nmc, ehin, eho, src, rev_index, dst, scat, do_relu);
    }
}

// round 8
// speedup vs baseline: 2.3202x; 1.5149x over previous
#include <cuda_runtime.h>
#include <cuda_bf16.h>
#include <cstdint>

// ChempropBlock: V=10000 nodes, E=160000 edges, D=512, DEPTH=3
// out = [node_hiddens (V*D) | eh (E*D)] fp32
//
// Per layer l:
//   nm_cur = segment_sum(relu(eh), dest)   (produced by previous epilogue / init)
//   ehout  = ehin + (nm_cur[src] - relu(ehin[rev])) @ W[l]^T + b[l]
//   epilogue scatters relu(ehout) into nm_next (plain into out_nodes last layer).
// GEMM: mma.sync m16n8k16 bf16 with a 3-term split (D += A0B0 + A1B0 + A0B1),
// a0 = bf16_rn(a), a1 = bf16_rn(a - a0): residual ~2^-18 -> rel_err ~1e-5.
// W split-fragments precomputed in gmem (k_wfrag); A rows gathered with
// per-thread cp.async into raw smem, converted/split to bf16 tiles in-kernel.

#define V_N 10000
#define E_N 160000
#define D_N 512
#define DEPTH_N 3

#define TM 128
#define TN 128
#define KC 32
#define NCHUNK (D_N / KC)     // 16

__device__ float g_nm0[(size_t)V_N * D_N];
__device__ float g_nm1[(size_t)V_N * D_N];
__device__ float g_eh[(size_t)E_N * D_N];
// W fragments: [layer(3)][nblock(4)][chunk(16)][k16(2)][nb(16)][lane(32)] uint4
__device__ uint4 g_wfrag[3 * 4 * 16 * 2 * 16 * 32];

__device__ __forceinline__ float4 relu4(float4 v) {
    v.x = fmaxf(v.x, 0.f); v.y = fmaxf(v.y, 0.f);
    v.z = fmaxf(v.z, 0.f); v.w = fmaxf(v.w, 0.f);
    return v;
}
__device__ __forceinline__ uint32_t smem_u32(const void* p) {
    uint32_t a;
    asm("{ .reg .u64 t; cvta.to.shared.u64 t, %1; cvt.u32.u64 %0, t; }"
        : "=r"(a) : "l"(p));
    return a;
}
// pack two floats -> bf16x2 (lo = x), and the bf16-rounded floats back
__device__ __forceinline__ uint32_t pack_bf2(float x, float y, float2& back) {
    __nv_bfloat162 h = __float22bfloat162_rn(make_float2(x, y));
    back = __bfloat1622float2(h);
    return *(uint32_t*)&h;
}
__device__ __forceinline__ uint32_t pack_bf2n(float x, float y) {
    __nv_bfloat162 h = __float22bfloat162_rn(make_float2(x, y));
    return *(uint32_t*)&h;
}

__device__ __forceinline__ void mma_bf16(float* d, const uint32_t* a,
                                         uint32_t b0, uint32_t b1) {
    asm volatile(
        "mma.sync.aligned.m16n8k16.row.col.f32.bf16.bf16.f32 "
        "{%0,%1,%2,%3}, {%4,%5,%6,%7}, {%8,%9}, {%0,%1,%2,%3};"
        : "+f"(d[0]), "+f"(d[1]), "+f"(d[2]), "+f"(d[3])
        : "r"(a[0]), "r"(a[1]), "r"(a[2]), "r"(a[3]), "r"(b0), "r"(b1));
}

#define CP_ASYNC_16(dst_u32, src_ptr) \
    asm volatile("cp.async.cg.shared.global [%0], [%1], 16;" \
                 :: "r"(dst_u32), "l"(src_ptr) : "memory")
#define CP_ASYNC_COMMIT() asm volatile("cp.async.commit_group;" ::: "memory")
#define CP_ASYNC_WAIT0()  asm volatile("cp.async.wait_group 0;" ::: "memory")

// ---------------------------------------------------------------------------
__global__ void k_zero_ptr(float4* __restrict__ p, int n4) {
    int i = blockIdx.x * blockDim.x + threadIdx.x;
    if (i < n4) p[i] = make_float4(0.f, 0.f, 0.f, 0.f);
}

// eh0 = nf[src] + ef ; relu-scatter eh0 into nm
__global__ void k_init_eh_scatter(const float* __restrict__ nf,
                                  const float* __restrict__ ef,
                                  const int* __restrict__ src,
                                  const int* __restrict__ dst,
                                  float* __restrict__ nm) {
    int idx = blockIdx.x * blockDim.x + threadIdx.x;   // < E*D/4
    int e = idx >> 7;
    int c = (idx & 127) << 2;
    int s = __ldg(&src[e]);
    const float4 a = *(const float4*)(nf + (size_t)s * D_N + c);
    const float4 b = *(const float4*)(ef + (size_t)e * D_N + c);
    float4 r; r.x = a.x + b.x; r.y = a.y + b.y; r.z = a.z + b.z; r.w = a.w + b.w;
    *(float4*)(g_eh + (size_t)e * D_N + c) = r;
    int d = __ldg(&dst[e]);
    float* p = nm + (size_t)d * D_N + c;
    atomicAdd(p + 0, fmaxf(r.x, 0.f));
    atomicAdd(p + 1, fmaxf(r.y, 0.f));
    atomicAdd(p + 2, fmaxf(r.z, 0.f));
    atomicAdd(p + 3, fmaxf(r.w, 0.f));
}

// Precompute bf16-split W fragments (m16n8k16 B operand layout, row.col).
// B reg b0 of lane l -> W[n = nb*8 + l/4][k = (l%4)*2 + {0,1}], b1 -> k+8.
// uint4 = { b0_split0, b1_split0, b0_split1, b1_split1 }.
__global__ void k_wfrag(const float* __restrict__ Ws) {
    int t = blockIdx.x * blockDim.x + threadIdx.x;     // < 196608
    int lane  = t & 31;
    int nb    = (t >> 5) & 15;
    int k16   = (t >> 9) & 1;
    int chunk = (t >> 10) & 15;
    int nblk  = (t >> 14) & 3;
    int layer = t >> 16;
    int n = nblk * 128 + nb * 8 + (lane >> 2);
    int k = chunk * 32 + k16 * 16 + (lane & 3) * 2;
    const float* w = Ws + ((size_t)layer * D_N + n) * D_N + k;
    float w00 = w[0], w01 = w[1], w10 = w[8], w11 = w[9];
    float2 bk;
    uint4 o;
    o.x = pack_bf2(w00, w01, bk);
    o.z = pack_bf2n(w00 - bk.x, w01 - bk.y);
    o.y = pack_bf2(w10, w11, bk);
    o.w = pack_bf2n(w10 - bk.x, w11 - bk.y);
    g_wfrag[t] = o;
}

// ---------------------------------------------------------------------------
// GEMM smem (b32 units):
//   [0..511]       s_src/s_rev/s_dst (128 ints each) + pad
//   RAWNM = 512    raw nm rows:  128 rows x 32 b32 (16B-granule swizzle g^=row&7)
//   RAWEH = 4608   raw eh rows
//   SA(st,sp) = 8704 + st*4096 + sp*2048 : bf16 A split tiles,
//                  [row][16 b32], 4B-idx swizzle: phys = idx ^ (((row>>1)&3)<<2)
//   SB(st)   = 16896 + st*4096 : W fragments [k16][nb][lane] uint4
// total 25088 b32 = 100352 B -> 2 CTA/SM
// ---------------------------------------------------------------------------
#define RAWNM 512
#define RAWEH 4608
#define SA_O(st, sp) (8704 + (st) * 4096 + (sp) * 2048)
#define SB_O(st)     (16896 + (st) * 4096)
#define SMEM_U32 25088

__global__ void __launch_bounds__(256, 2)
k_gemm_mma(const uint4* __restrict__ wf,       // this layer's fragment table
           const float* __restrict__ bias,
           const float* __restrict__ nm,
           const float* __restrict__ ehin,
           float* __restrict__ ehout,
           const int* __restrict__ src,
           const int* __restrict__ rev,
           const int* __restrict__ dst,
           float* __restrict__ scat,
           int do_relu) {
    extern __shared__ float smemf[];
    uint32_t* smemu = (uint32_t*)smemf;
    int* s_src = (int*)smemf;
    int* s_rev = (int*)smemf + 128;
    int* s_dst = (int*)smemf + 256;

    const int tid = threadIdx.x;
    const int wid = tid >> 5;
    const int lid = tid & 31;
    const int mBase = blockIdx.y * TM;
    const int nBase = blockIdx.x * TN;
    const uint4* wfn = wf + (size_t)blockIdx.x * (NCHUNK * 1024); // 1024 uint4/chunk

    if (tid < TM) {
        s_src[tid] = __ldg(&src[mBase + tid]);
        s_rev[tid] = __ldg(&rev[mBase + tid]);
        s_dst[tid] = __ldg(&dst[mBase + tid]);
    }
    __syncthreads();

    const uint32_t sb = smem_u32(smemf);

    // staging coords: 8 threads per row, 16B each, 4 row-passes
    const int strow0 = tid >> 3;      // 0..31
    const int kp     = tid & 7;       // 16B granule in 128B row

    uint32_t rawDstN[4], rawDstE[4];
    const float* gsrcN[4];
    const float* gsrcE[4];
#pragma unroll
    for (int p = 0; p < 4; ++p) {
        const int row = strow0 + 32 * p;
        const int g = kp ^ (row & 7);
        rawDstN[p] = sb + (RAWNM + row * 32 + g * 4) * 4;
        rawDstE[p] = sb + (RAWEH + row * 32 + g * 4) * 4;
        gsrcN[p] = nm + (size_t)s_src[row] * D_N + kp * 4;
        gsrcE[p] = ehin + (size_t)s_rev[row] * D_N + kp * 4;
    }

    auto issue_raw = [&](int c) {
        const int ko = c * KC;
#pragma unroll
        for (int p = 0; p < 4; ++p) {
            CP_ASYNC_16(rawDstN[p], gsrcN[p] + ko);
            CP_ASYNC_16(rawDstE[p], gsrcE[p] + ko);
        }
    };
    auto issue_B = [&](int c, int st) {
        const uint32_t dbase = sb + SB_O(st) * 4;
        const uint4* sB = wfn + c * 1024;
#pragma unroll
        for (int q = 0; q < 4; ++q) {
            const int i = tid + q * 256;
            CP_ASYNC_16(dbase + i * 16, sB + i);
        }
    };
    // convert raw -> bf16 split tiles
    auto convert = [&](int st) {
        const int sa0 = SA_O(st, 0);
        const int sa1 = SA_O(st, 1);
#pragma unroll
        for (int p = 0; p < 4; ++p) {
            const int row = strow0 + 32 * p;
            const int g = kp ^ (row & 7);
            const float4 n4 = *(const float4*)(smemf + RAWNM + row * 32 + g * 4);
            const float4 e4 = *(const float4*)(smemf + RAWEH + row * 32 + g * 4);
            float em0 = n4.x - fmaxf(e4.x, 0.f);
            float em1 = n4.y - fmaxf(e4.y, 0.f);
            float em2 = n4.z - fmaxf(e4.z, 0.f);
            float em3 = n4.w - fmaxf(e4.w, 0.f);
            float2 bk;
            uint2 s0, s1;
            s0.x = pack_bf2(em0, em1, bk);
            s1.x = pack_bf2n(em0 - bk.x, em1 - bk.y);
            s0.y = pack_bf2(em2, em3, bk);
            s1.y = pack_bf2n(em2 - bk.x, em3 - bk.y);
            const int sw = ((row >> 1) & 3) << 2;
            const int off = row * 16 + ((2 * kp) ^ sw);
            *(uint2*)(smemu + sa0 + off) = s0;
            *(uint2*)(smemu + sa1 + off) = s1;
        }
    };

    // ---- warp tiles: 2 (M) x 4 (N) of 64x32 ----
    const int wm  = (wid >> 2) * 64;
    const int wnb = (wid & 3) * 4;      // nb base (each nb = 8 cols)
    const int wn  = wnb * 8;

    float acc[4][4][4];
#pragma unroll
    for (int i = 0; i < 4; ++i)
#pragma unroll
        for (int j = 0; j < 4; ++j)
#pragma unroll
            for (int k = 0; k < 4; ++k) acc[i][j][k] = 0.f;

    // prologue
    issue_raw(0);
    issue_B(0, 0);
    CP_ASYNC_COMMIT();
    CP_ASYNC_WAIT0();
    __syncthreads();

    for (int c = 0; c < NCHUNK; ++c) {
        const int st = c & 1;
        convert(st);
        __syncthreads();
        if (c + 1 < NCHUNK) {
            issue_raw(c + 1);
            issue_B(c + 1, st ^ 1);
            CP_ASYNC_COMMIT();
        }

        // MMA on stage st
#pragma unroll
        for (int k16 = 0; k16 < 2; ++k16) {
            uint4 b[4];
#pragma unroll
            for (int nb = 0; nb < 4; ++nb)
                b[nb] = *(const uint4*)(smemu + SB_O(st) +
                         ((k16 * 16 + wnb + nb) * 32 + lid) * 4);
#pragma unroll
            for (int rbi = 0; rbi < 4; ++rbi) {
                const int rowa = wm + rbi * 16 + (lid >> 2);
                const int sw = ((rowa >> 1) & 3) << 2;
                const int p0 = (k16 * 8 + (lid & 3)) ^ sw;
                const int p1 = p0 ^ 4;     // idx+4, sw only bits 2-3 -> xor ok? no:
                // (idx+4)^sw == (idx^sw)+4 only if bit2 of idx^... compute directly:
                const int q1 = (k16 * 8 + (lid & 3) + 4) ^ sw;
                const uint32_t* A0 = smemu + SA_O(st, 0) + rowa * 16;
                uint32_t as0[4] = { A0[p0], A0[128 + p0], A0[q1], A0[128 + q1] };
                const uint32_t* A1 = A0 + 2048;
                uint32_t as1[4] = { A1[p0], A1[128 + p0], A1[q1], A1[128 + q1] };
#pragma unroll
                for (int nb = 0; nb < 4; ++nb)
                    mma_bf16(acc[rbi][nb], as0, b[nb].x, b[nb].y);
#pragma unroll
                for (int nb = 0; nb < 4; ++nb)
                    mma_bf16(acc[rbi][nb], as1, b[nb].x, b[nb].y);
#pragma unroll
                for (int nb = 0; nb < 4; ++nb)
                    mma_bf16(acc[rbi][nb], as0, b[nb].z, b[nb].w);
                (void)p1;
            }
        }

        if (c + 1 < NCHUNK) CP_ASYNC_WAIT0();
        __syncthreads();
    }

    // ---- epilogue: ehout = ehin + acc + bias; fused scatter ----
    const int lr4 = lid >> 2;
    const int lm4 = lid & 3;
#pragma unroll
    for (int rbi = 0; rbi < 4; ++rbi) {
#pragma unroll
        for (int half = 0; half < 2; ++half) {
            const int mi = wm + rbi * 16 + half * 8 + lr4;
            const int m = mBase + mi;
            const int d = s_dst[mi];
            const float* ein = ehin + (size_t)m * D_N + nBase;
            float* eout = ehout + (size_t)m * D_N + nBase;
            float* srow = scat + (size_t)d * D_N + nBase;
#pragma unroll
            for (int nb = 0; nb < 4; ++nb) {
                const int cc = wn + nb * 8 + 2 * lm4;
                float2 e = *(const float2*)(ein + cc);
                e.x += acc[rbi][nb][half * 2 + 0] + __ldg(&bias[nBase + cc]);
                e.y += acc[rbi][nb][half * 2 + 1] + __ldg(&bias[nBase + cc + 1]);
                *(float2*)(eout + cc) = e;
                if (do_relu) {
                    atomicAdd(srow + cc,     fmaxf(e.x, 0.f));
                    atomicAdd(srow + cc + 1, fmaxf(e.y, 0.f));
                } else {
                    atomicAdd(srow + cc,     e.x);
                    atomicAdd(srow + cc + 1, e.y);
                }
            }
        }
    }
}

// ---------------------------------------------------------------------------
extern "C" void kernel_launch(void* const* d_in, const int* in_sizes, int n_in,
                              void* d_out, int out_size) {
    const float* node_feats = (const float*)d_in[0];
    const float* edge_feats = (const float*)d_in[1];
    const float* Ws         = (const float*)d_in[2];
    const float* bs         = (const float*)d_in[3];
    const int*   edge_index = (const int*)  d_in[4];
    const int*   rev_index  = (const int*)  d_in[5];

    const int* src = edge_index;
    const int* dst = edge_index + E_N;

    float* out_nodes = (float*)d_out;
    float* eh_out    = (float*)d_out + (size_t)V_N * D_N;

    float *eh_scratch = nullptr, *nm0 = nullptr, *nm1 = nullptr;
    uint4* wfrag = nullptr;
    cudaGetSymbolAddress((void**)&eh_scratch, g_eh);
    cudaGetSymbolAddress((void**)&nm0, g_nm0);
    cudaGetSymbolAddress((void**)&nm1, g_nm1);
    cudaGetSymbolAddress((void**)&wfrag, g_wfrag);

    const int smem_bytes = SMEM_U32 * 4;    // 100352
    cudaFuncSetAttribute(k_gemm_mma,
                         cudaFuncAttributeMaxDynamicSharedMemorySize, smem_bytes);

    const int TPB = 256;
    const int edgeGrid = (E_N * (D_N / 4)) / TPB;   // 80000
    const int nmGrid   = (V_N * (D_N / 4)) / TPB;   // 5000
    dim3 gemmGrid(D_N / TN, E_N / TM);              // (4, 1250)

    // W fragment precompute (all 3 layers): 196608 threads
    k_wfrag<<<768, 256>>>(Ws);

    k_zero_ptr<<<nmGrid, TPB>>>((float4*)nm0, V_N * D_N / 4);
    k_init_eh_scatter<<<edgeGrid, TPB>>>(node_feats, edge_feats, src, dst, nm0);

    float* ehbufs[2] = { eh_scratch, eh_out };
    float* nmbufs[2] = { nm0, nm1 };
    const int frag_per_layer = 4 * NCHUNK * 1024;   // uint4 per layer
    for (int l = 0; l < DEPTH_N; ++l) {
        const float* ehin = ehbufs[l & 1];
        float*       eho  = ehbufs[(l + 1) & 1];
        const float* nmc  = nmbufs[l & 1];
        float*       scat;
        int          do_relu;
        if (l + 1 < DEPTH_N) {
            scat = nmbufs[(l + 1) & 1];
            do_relu = 1;
            k_zero_ptr<<<nmGrid, TPB>>>((float4*)scat, V_N * D_N / 4);
        } else {
            scat = out_nodes;
            do_relu = 0;
            k_zero_ptr<<<nmGrid, TPB>>>((float4*)out_nodes, V_N * D_N / 4);
        }
        k_gemm_mma<<<gemmGrid, TPB, smem_bytes>>>(
            wfrag + (size_t)l * frag_per_layer, bs + (size_t)l * D_N,
            nmc, ehin, eho, src, rev_index, dst, scat, do_relu);
    }
}

// round 9
// speedup vs baseline: 2.7743x; 1.1957x over previous
#include <cuda_runtime.h>
#include <cuda_bf16.h>
#include <cstdint>

// ChempropBlock: V=10000 nodes, E=160000 edges, D=512, DEPTH=3
// out = [node_hiddens (V*D) | eh (E*D)] fp32
//
// Per layer l:
//   nm_cur = segment_sum(relu(eh), dest)   (produced by previous epilogue / init)
//   ehout  = ehin + (nm_cur[src] - relu(ehin[rev])) @ W[l]^T + b[l]
//   epilogue scatters relu(ehout) into nm_next (plain into out_nodes last layer).
// GEMM: mma.sync m16n8k16 bf16, 3-term split (D += A0B0 + A1B0 + A0B1).
// R9: single-syncthreads chunk pipeline (convert overlaps other warps' MMAs),
// vector red.global atomics in the scatter paths.

#define V_N 10000
#define E_N 160000
#define D_N 512
#define DEPTH_N 3

#define TM 128
#define TN 128
#define KC 32
#define NCHUNK (D_N / KC)     // 16

__device__ float g_nm0[(size_t)V_N * D_N];
__device__ float g_nm1[(size_t)V_N * D_N];
__device__ float g_eh[(size_t)E_N * D_N];
// W fragments: [layer(3)][nblock(4)][chunk(16)][k16(2)][nb(16)][lane(32)] uint4
__device__ uint4 g_wfrag[3 * 4 * 16 * 2 * 16 * 32];

__device__ __forceinline__ uint32_t smem_u32(const void* p) {
    uint32_t a;
    asm("{ .reg .u64 t; cvta.to.shared.u64 t, %1; cvt.u32.u64 %0, t; }"
        : "=r"(a) : "l"(p));
    return a;
}
__device__ __forceinline__ uint32_t pack_bf2(float x, float y, float2& back) {
    __nv_bfloat162 h = __float22bfloat162_rn(make_float2(x, y));
    back = __bfloat1622float2(h);
    return *(uint32_t*)&h;
}
__device__ __forceinline__ uint32_t pack_bf2n(float x, float y) {
    __nv_bfloat162 h = __float22bfloat162_rn(make_float2(x, y));
    return *(uint32_t*)&h;
}
__device__ __forceinline__ void red_add_v4(float* addr, float4 v) {
    asm volatile("red.global.add.v4.f32 [%0], {%1, %2, %3, %4};"
                 :: "l"(addr), "f"(v.x), "f"(v.y), "f"(v.z), "f"(v.w)
                 : "memory");
}
__device__ __forceinline__ void red_add_v2(float* addr, float x, float y) {
    asm volatile("red.global.add.v2.f32 [%0], {%1, %2};"
                 :: "l"(addr), "f"(x), "f"(y)
                 : "memory");
}

__device__ __forceinline__ void mma_bf16(float* d, const uint32_t* a,
                                         uint32_t b0, uint32_t b1) {
    asm volatile(
        "mma.sync.aligned.m16n8k16.row.col.f32.bf16.bf16.f32 "
        "{%0,%1,%2,%3}, {%4,%5,%6,%7}, {%8,%9}, {%0,%1,%2,%3};"
        : "+f"(d[0]), "+f"(d[1]), "+f"(d[2]), "+f"(d[3])
        : "r"(a[0]), "r"(a[1]), "r"(a[2]), "r"(a[3]), "r"(b0), "r"(b1));
}

#define CP_ASYNC_16(dst_u32, src_ptr) \
    asm volatile("cp.async.cg.shared.global [%0], [%1], 16;" \
                 :: "r"(dst_u32), "l"(src_ptr) : "memory")
#define CP_ASYNC_COMMIT() asm volatile("cp.async.commit_group;" ::: "memory")
#define CP_ASYNC_WAIT0()  asm volatile("cp.async.wait_group 0;" ::: "memory")

// ---------------------------------------------------------------------------
__global__ void k_zero_ptr(float4* __restrict__ p, int n4) {
    int i = blockIdx.x * blockDim.x + threadIdx.x;
    if (i < n4) p[i] = make_float4(0.f, 0.f, 0.f, 0.f);
}

// eh0 = nf[src] + ef ; relu-scatter eh0 into nm
__global__ void k_init_eh_scatter(const float* __restrict__ nf,
                                  const float* __restrict__ ef,
                                  const int* __restrict__ src,
                                  const int* __restrict__ dst,
                                  float* __restrict__ nm) {
    int idx = blockIdx.x * blockDim.x + threadIdx.x;   // < E*D/4
    int e = idx >> 7;
    int c = (idx & 127) << 2;
    int s = __ldg(&src[e]);
    const float4 a = *(const float4*)(nf + (size_t)s * D_N + c);
    const float4 b = *(const float4*)(ef + (size_t)e * D_N + c);
    float4 r; r.x = a.x + b.x; r.y = a.y + b.y; r.z = a.z + b.z; r.w = a.w + b.w;
    *(float4*)(g_eh + (size_t)e * D_N + c) = r;
    int d = __ldg(&dst[e]);
    float4 rr;
    rr.x = fmaxf(r.x, 0.f); rr.y = fmaxf(r.y, 0.f);
    rr.z = fmaxf(r.z, 0.f); rr.w = fmaxf(r.w, 0.f);
    red_add_v4(nm + (size_t)d * D_N + c, rr);
}

// Precompute bf16-split W fragments (m16n8k16 B operand layout, row.col).
// B reg b0 of lane l -> W[n = nb*8 + l/4][k = (l%4)*2 + {0,1}], b1 -> k+8.
// uint4 = { b0_split0, b1_split0, b0_split1, b1_split1 }.
__global__ void k_wfrag(const float* __restrict__ Ws) {
    int t = blockIdx.x * blockDim.x + threadIdx.x;     // < 196608
    int lane  = t & 31;
    int nb    = (t >> 5) & 15;
    int k16   = (t >> 9) & 1;
    int chunk = (t >> 10) & 15;
    int nblk  = (t >> 14) & 3;
    int layer = t >> 16;
    int n = nblk * 128 + nb * 8 + (lane >> 2);
    int k = chunk * 32 + k16 * 16 + (lane & 3) * 2;
    const float* w = Ws + ((size_t)layer * D_N + n) * D_N + k;
    float w00 = w[0], w01 = w[1], w10 = w[8], w11 = w[9];
    float2 bk;
    uint4 o;
    o.x = pack_bf2(w00, w01, bk);
    o.z = pack_bf2n(w00 - bk.x, w01 - bk.y);
    o.y = pack_bf2(w10, w11, bk);
    o.w = pack_bf2n(w10 - bk.x, w11 - bk.y);
    g_wfrag[t] = o;
}

// ---------------------------------------------------------------------------
// GEMM smem (b32 units):
//   [0..511]       s_src/s_rev/s_dst (128 ints each) + pad
//   RAWNM = 512    raw nm rows:  128 rows x 32 b32 (16B-granule swizzle g^=row&7)
//   RAWEH = 4608   raw eh rows
//   SA(st,sp) = 8704 + st*4096 + sp*2048 : bf16 A split tiles,
//                  [row][16 b32], 4B-idx swizzle: phys = idx ^ (((row>>1)&3)<<2)
//   SB(st)   = 16896 + st*4096 : W fragments [k16][nb][lane] uint4
// total 25088 b32 = 100352 B -> 2 CTA/SM
// ---------------------------------------------------------------------------
#define RAWNM 512
#define RAWEH 4608
#define SA_O(st, sp) (8704 + (st) * 4096 + (sp) * 2048)
#define SB_O(st)     (16896 + (st) * 4096)
#define SMEM_U32 25088

__global__ void __launch_bounds__(256, 2)
k_gemm_mma(const uint4* __restrict__ wf,       // this layer's fragment table
           const float* __restrict__ bias,
           const float* __restrict__ nm,
           const float* __restrict__ ehin,
           float* __restrict__ ehout,
           const int* __restrict__ src,
           const int* __restrict__ rev,
           const int* __restrict__ dst,
           float* __restrict__ scat,
           int do_relu) {
    extern __shared__ float smemf[];
    uint32_t* smemu = (uint32_t*)smemf;
    int* s_src = (int*)smemf;
    int* s_rev = (int*)smemf + 128;
    int* s_dst = (int*)smemf + 256;

    const int tid = threadIdx.x;
    const int wid = tid >> 5;
    const int lid = tid & 31;
    const int mBase = blockIdx.y * TM;
    const int nBase = blockIdx.x * TN;
    const uint4* wfn = wf + (size_t)blockIdx.x * (NCHUNK * 1024); // 1024 uint4/chunk

    if (tid < TM) {
        s_src[tid] = __ldg(&src[mBase + tid]);
        s_rev[tid] = __ldg(&rev[mBase + tid]);
        s_dst[tid] = __ldg(&dst[mBase + tid]);
    }
    __syncthreads();

    const uint32_t sb = smem_u32(smemf);

    // staging coords: 8 threads per row, 16B each, 4 row-passes
    const int strow0 = tid >> 3;      // 0..31
    const int kp     = tid & 7;       // 16B granule in 128B row

    uint32_t rawDstN[4], rawDstE[4];
    const float* gsrcN[4];
    const float* gsrcE[4];
#pragma unroll
    for (int p = 0; p < 4; ++p) {
        const int row = strow0 + 32 * p;
        const int g = kp ^ (row & 7);
        rawDstN[p] = sb + (RAWNM + row * 32 + g * 4) * 4;
        rawDstE[p] = sb + (RAWEH + row * 32 + g * 4) * 4;
        gsrcN[p] = nm + (size_t)s_src[row] * D_N + kp * 4;
        gsrcE[p] = ehin + (size_t)s_rev[row] * D_N + kp * 4;
    }

    auto issue_raw = [&](int c) {
        const int ko = c * KC;
#pragma unroll
        for (int p = 0; p < 4; ++p) {
            CP_ASYNC_16(rawDstN[p], gsrcN[p] + ko);
            CP_ASYNC_16(rawDstE[p], gsrcE[p] + ko);
        }
    };
    auto issue_B = [&](int c, int st) {
        const uint32_t dbase = sb + SB_O(st) * 4;
        const uint4* sBp = wfn + c * 1024;
#pragma unroll
        for (int q = 0; q < 4; ++q) {
            const int i = tid + q * 256;
            CP_ASYNC_16(dbase + i * 16, sBp + i);
        }
    };
    // convert raw -> bf16 split tiles (SA stage st)
    auto convert = [&](int st) {
        const int sa0 = SA_O(st, 0);
        const int sa1 = SA_O(st, 1);
#pragma unroll
        for (int p = 0; p < 4; ++p) {
            const int row = strow0 + 32 * p;
            const int g = kp ^ (row & 7);
            const float4 n4 = *(const float4*)(smemf + RAWNM + row * 32 + g * 4);
            const float4 e4 = *(const float4*)(smemf + RAWEH + row * 32 + g * 4);
            float em0 = n4.x - fmaxf(e4.x, 0.f);
            float em1 = n4.y - fmaxf(e4.y, 0.f);
            float em2 = n4.z - fmaxf(e4.z, 0.f);
            float em3 = n4.w - fmaxf(e4.w, 0.f);
            float2 bk;
            uint2 s0, s1;
            s0.x = pack_bf2(em0, em1, bk);
            s1.x = pack_bf2n(em0 - bk.x, em1 - bk.y);
            s0.y = pack_bf2(em2, em3, bk);
            s1.y = pack_bf2n(em2 - bk.x, em3 - bk.y);
            const int sw = ((row >> 1) & 3) << 2;
            const int off = row * 16 + ((2 * kp) ^ sw);
            *(uint2*)(smemu + sa0 + off) = s0;
            *(uint2*)(smemu + sa1 + off) = s1;
        }
    };

    // ---- warp tiles: 2 (M) x 4 (N) of 64x32 ----
    const int wm  = (wid >> 2) * 64;
    const int wnb = (wid & 3) * 4;      // nb base (each nb = 8 cols)
    const int wn  = wnb * 8;

    float acc[4][4][4];
#pragma unroll
    for (int i = 0; i < 4; ++i)
#pragma unroll
        for (int j = 0; j < 4; ++j)
#pragma unroll
            for (int k = 0; k < 4; ++k) acc[i][j][k] = 0.f;

    // prologue: gathers + B for chunk 0 in flight
    issue_raw(0);
    issue_B(0, 0);
    CP_ASYNC_COMMIT();

    // Single-sync chunk pipeline:
    //   wait(group c) -> convert(c) -> sync -> issue(c+1) -> MMA(c)
    // convert(c) overlaps other warps' MMA(c-1); issue comes after the barrier
    // so no cp.async write can race a convert read (RAW buf) or MMA read (SB).
    for (int c = 0; c < NCHUNK; ++c) {
        const int st = c & 1;
        CP_ASYNC_WAIT0();               // raw(c) + B(c) arrived
        convert(st);
        __syncthreads();
        if (c + 1 < NCHUNK) {
            issue_raw(c + 1);
            issue_B(c + 1, st ^ 1);
            CP_ASYNC_COMMIT();
        }

        // MMA on stage st
#pragma unroll
        for (int k16 = 0; k16 < 2; ++k16) {
            uint4 b[4];
#pragma unroll
            for (int nb = 0; nb < 4; ++nb)
                b[nb] = *(const uint4*)(smemu + SB_O(st) +
                         ((k16 * 16 + wnb + nb) * 32 + lid) * 4);
#pragma unroll
            for (int rbi = 0; rbi < 4; ++rbi) {
                const int rowa = wm + rbi * 16 + (lid >> 2);
                const int sw = ((rowa >> 1) & 3) << 2;
                const int p0 = (k16 * 8 + (lid & 3)) ^ sw;
                const int q1 = (k16 * 8 + (lid & 3) + 4) ^ sw;
                const uint32_t* A0 = smemu + SA_O(st, 0) + rowa * 16;
                uint32_t as0[4] = { A0[p0], A0[128 + p0], A0[q1], A0[128 + q1] };
                const uint32_t* A1 = A0 + 2048;
                uint32_t as1[4] = { A1[p0], A1[128 + p0], A1[q1], A1[128 + q1] };
#pragma unroll
                for (int nb = 0; nb < 4; ++nb)
                    mma_bf16(acc[rbi][nb], as0, b[nb].x, b[nb].y);
#pragma unroll
                for (int nb = 0; nb < 4; ++nb)
                    mma_bf16(acc[rbi][nb], as1, b[nb].x, b[nb].y);
#pragma unroll
                for (int nb = 0; nb < 4; ++nb)
                    mma_bf16(acc[rbi][nb], as0, b[nb].z, b[nb].w);
            }
        }
    }

    // ---- epilogue: ehout = ehin + acc + bias; fused scatter (vector RED) ----
    const int lr4 = lid >> 2;
    const int lm4 = lid & 3;
#pragma unroll
    for (int rbi = 0; rbi < 4; ++rbi) {
#pragma unroll
        for (int half = 0; half < 2; ++half) {
            const int mi = wm + rbi * 16 + half * 8 + lr4;
            const int m = mBase + mi;
            const int d = s_dst[mi];
            const float* ein = ehin + (size_t)m * D_N + nBase;
            float* eout = ehout + (size_t)m * D_N + nBase;
            float* srow = scat + (size_t)d * D_N + nBase;
#pragma unroll
            for (int nb = 0; nb < 4; ++nb) {
                const int cc = wn + nb * 8 + 2 * lm4;
                float2 e = *(const float2*)(ein + cc);
                e.x += acc[rbi][nb][half * 2 + 0] + __ldg(&bias[nBase + cc]);
                e.y += acc[rbi][nb][half * 2 + 1] + __ldg(&bias[nBase + cc + 1]);
                *(float2*)(eout + cc) = e;
                if (do_relu) {
                    red_add_v2(srow + cc, fmaxf(e.x, 0.f), fmaxf(e.y, 0.f));
                } else {
                    red_add_v2(srow + cc, e.x, e.y);
                }
            }
        }
    }
}

// ---------------------------------------------------------------------------
extern "C" void kernel_launch(void* const* d_in, const int* in_sizes, int n_in,
                              void* d_out, int out_size) {
    const float* node_feats = (const float*)d_in[0];
    const float* edge_feats = (const float*)d_in[1];
    const float* Ws         = (const float*)d_in[2];
    const float* bs         = (const float*)d_in[3];
    const int*   edge_index = (const int*)  d_in[4];
    const int*   rev_index  = (const int*)  d_in[5];

    const int* src = edge_index;
    const int* dst = edge_index + E_N;

    float* out_nodes = (float*)d_out;
    float* eh_out    = (float*)d_out + (size_t)V_N * D_N;

    float *eh_scratch = nullptr, *nm0 = nullptr, *nm1 = nullptr;
    uint4* wfrag = nullptr;
    cudaGetSymbolAddress((void**)&eh_scratch, g_eh);
    cudaGetSymbolAddress((void**)&nm0, g_nm0);
    cudaGetSymbolAddress((void**)&nm1, g_nm1);
    cudaGetSymbolAddress((void**)&wfrag, g_wfrag);

    const int smem_bytes = SMEM_U32 * 4;    // 100352
    cudaFuncSetAttribute(k_gemm_mma,
                         cudaFuncAttributeMaxDynamicSharedMemorySize, smem_bytes);

    const int TPB = 256;
    const int edgeGrid = (E_N * (D_N / 4)) / TPB;   // 80000
    const int nmGrid   = (V_N * (D_N / 4)) / TPB;   // 5000
    dim3 gemmGrid(D_N / TN, E_N / TM);              // (4, 1250)

    // W fragment precompute (all 3 layers)
    k_wfrag<<<768, 256>>>(Ws);

    k_zero_ptr<<<nmGrid, TPB>>>((float4*)nm0, V_N * D_N / 4);
    k_init_eh_scatter<<<edgeGrid, TPB>>>(node_feats, edge_feats, src, dst, nm0);

    float* ehbufs[2] = { eh_scratch, eh_out };
    float* nmbufs[2] = { nm0, nm1 };
    const int frag_per_layer = 4 * NCHUNK * 1024;   // uint4 per layer
    for (int l = 0; l < DEPTH_N; ++l) {
        const float* ehin = ehbufs[l & 1];
        float*       eho  = ehbufs[(l + 1) & 1];
        const float* nmc  = nmbufs[l & 1];
        float*       scat;
        int          do_relu;
        if (l + 1 < DEPTH_N) {
            scat = nmbufs[(l + 1) & 1];
            do_relu = 1;
            k_zero_ptr<<<nmGrid, TPB>>>((float4*)scat, V_N * D_N / 4);
        } else {
            scat = out_nodes;
            do_relu = 0;
            k_zero_ptr<<<nmGrid, TPB>>>((float4*)out_nodes, V_N * D_N / 4);
        }
        k_gemm_mma<<<gemmGrid, TPB, smem_bytes>>>(
            wfrag + (size_t)l * frag_per_layer, bs + (size_t)l * D_N,
            nmc, ehin, eho, src, rev_index, dst, scat, do_relu);
    }
}

// round 10
// speedup vs baseline: 2.8254x; 1.0184x over previous
#include <cuda_runtime.h>
#include <cuda_bf16.h>
#include <cstdint>

// ChempropBlock: V=10000 nodes, E=160000 edges, D=512, DEPTH=3
// out = [node_hiddens (V*D) | eh (E*D)] fp32
//
// Per layer l:
//   nm_cur = segment_sum(relu(eh), dest)   (produced by previous epilogue / init)
//   ehout  = ehin + (nm_cur[src] - relu(ehin[rev])) @ W[l]^T + b[l]
//   epilogue scatters relu(ehout) into nm_next (plain into out_nodes last layer).
// GEMM: mma.sync m16n8k16 bf16, 3-term split (D += A0B0 + A1B0 + A0B1).
// R10: A fragments loaded via ldmatrix.m8n8.x4.b16 (1 LDSM replaces 8 LDS.32).

#define V_N 10000
#define E_N 160000
#define D_N 512
#define DEPTH_N 3

#define TM 128
#define TN 128
#define KC 32
#define NCHUNK (D_N / KC)     // 16

__device__ float g_nm0[(size_t)V_N * D_N];
__device__ float g_nm1[(size_t)V_N * D_N];
__device__ float g_eh[(size_t)E_N * D_N];
// W fragments: [layer(3)][nblock(4)][chunk(16)][k16(2)][nb(16)][lane(32)] uint4
__device__ uint4 g_wfrag[3 * 4 * 16 * 2 * 16 * 32];

__device__ __forceinline__ uint32_t smem_u32(const void* p) {
    uint32_t a;
    asm("{ .reg .u64 t; cvta.to.shared.u64 t, %1; cvt.u32.u64 %0, t; }"
        : "=r"(a) : "l"(p));
    return a;
}
__device__ __forceinline__ uint32_t pack_bf2(float x, float y, float2& back) {
    __nv_bfloat162 h = __float22bfloat162_rn(make_float2(x, y));
    back = __bfloat1622float2(h);
    return *(uint32_t*)&h;
}
__device__ __forceinline__ uint32_t pack_bf2n(float x, float y) {
    __nv_bfloat162 h = __float22bfloat162_rn(make_float2(x, y));
    return *(uint32_t*)&h;
}
__device__ __forceinline__ void red_add_v4(float* addr, float4 v) {
    asm volatile("red.global.add.v4.f32 [%0], {%1, %2, %3, %4};"
                 :: "l"(addr), "f"(v.x), "f"(v.y), "f"(v.z), "f"(v.w)
                 : "memory");
}
__device__ __forceinline__ void red_add_v2(float* addr, float x, float y) {
    asm volatile("red.global.add.v2.f32 [%0], {%1, %2};"
                 :: "l"(addr), "f"(x), "f"(y)
                 : "memory");
}
__device__ __forceinline__ void ldmatrix_x4(uint32_t* r, uint32_t addr) {
    asm volatile("ldmatrix.sync.aligned.m8n8.x4.shared.b16 {%0,%1,%2,%3}, [%4];"
                 : "=r"(r[0]), "=r"(r[1]), "=r"(r[2]), "=r"(r[3])
                 : "r"(addr));
}

__device__ __forceinline__ void mma_bf16(float* d, const uint32_t* a,
                                         uint32_t b0, uint32_t b1) {
    asm volatile(
        "mma.sync.aligned.m16n8k16.row.col.f32.bf16.bf16.f32 "
        "{%0,%1,%2,%3}, {%4,%5,%6,%7}, {%8,%9}, {%0,%1,%2,%3};"
        : "+f"(d[0]), "+f"(d[1]), "+f"(d[2]), "+f"(d[3])
        : "r"(a[0]), "r"(a[1]), "r"(a[2]), "r"(a[3]), "r"(b0), "r"(b1));
}

#define CP_ASYNC_16(dst_u32, src_ptr) \
    asm volatile("cp.async.cg.shared.global [%0], [%1], 16;" \
                 :: "r"(dst_u32), "l"(src_ptr) : "memory")
#define CP_ASYNC_COMMIT() asm volatile("cp.async.commit_group;" ::: "memory")
#define CP_ASYNC_WAIT0()  asm volatile("cp.async.wait_group 0;" ::: "memory")

// ---------------------------------------------------------------------------
__global__ void k_zero_ptr(float4* __restrict__ p, int n4) {
    int i = blockIdx.x * blockDim.x + threadIdx.x;
    if (i < n4) p[i] = make_float4(0.f, 0.f, 0.f, 0.f);
}

// eh0 = nf[src] + ef ; relu-scatter eh0 into nm
__global__ void k_init_eh_scatter(const float* __restrict__ nf,
                                  const float* __restrict__ ef,
                                  const int* __restrict__ src,
                                  const int* __restrict__ dst,
                                  float* __restrict__ nm) {
    int idx = blockIdx.x * blockDim.x + threadIdx.x;   // < E*D/4
    int e = idx >> 7;
    int c = (idx & 127) << 2;
    int s = __ldg(&src[e]);
    const float4 a = *(const float4*)(nf + (size_t)s * D_N + c);
    const float4 b = *(const float4*)(ef + (size_t)e * D_N + c);
    float4 r; r.x = a.x + b.x; r.y = a.y + b.y; r.z = a.z + b.z; r.w = a.w + b.w;
    *(float4*)(g_eh + (size_t)e * D_N + c) = r;
    int d = __ldg(&dst[e]);
    float4 rr;
    rr.x = fmaxf(r.x, 0.f); rr.y = fmaxf(r.y, 0.f);
    rr.z = fmaxf(r.z, 0.f); rr.w = fmaxf(r.w, 0.f);
    red_add_v4(nm + (size_t)d * D_N + c, rr);
}

// Precompute bf16-split W fragments (m16n8k16 B operand layout, row.col).
__global__ void k_wfrag(const float* __restrict__ Ws) {
    int t = blockIdx.x * blockDim.x + threadIdx.x;     // < 196608
    int lane  = t & 31;
    int nb    = (t >> 5) & 15;
    int k16   = (t >> 9) & 1;
    int chunk = (t >> 10) & 15;
    int nblk  = (t >> 14) & 3;
    int layer = t >> 16;
    int n = nblk * 128 + nb * 8 + (lane >> 2);
    int k = chunk * 32 + k16 * 16 + (lane & 3) * 2;
    const float* w = Ws + ((size_t)layer * D_N + n) * D_N + k;
    float w00 = w[0], w01 = w[1], w10 = w[8], w11 = w[9];
    float2 bk;
    uint4 o;
    o.x = pack_bf2(w00, w01, bk);
    o.z = pack_bf2n(w00 - bk.x, w01 - bk.y);
    o.y = pack_bf2(w10, w11, bk);
    o.w = pack_bf2n(w10 - bk.x, w11 - bk.y);
    g_wfrag[t] = o;
}

// ---------------------------------------------------------------------------
// GEMM smem (b32 units):
//   [0..511]       s_src/s_rev/s_dst (128 ints each) + pad
//   RAWNM = 512    raw nm rows:  128 rows x 32 b32 (16B-granule swizzle g^=row&7)
//   RAWEH = 4608   raw eh rows
//   SA(st,sp) = 8704 + st*4096 + sp*2048 : bf16 A split tiles,
//                  [row][16 b32], 4B-idx swizzle: phys = idx ^ (((row>>1)&3)<<2)
//   SB(st)   = 16896 + st*4096 : W fragments [k16][nb][lane] uint4
// total 25088 b32 = 100352 B -> 2 CTA/SM
// ---------------------------------------------------------------------------
#define RAWNM 512
#define RAWEH 4608
#define SA_O(st, sp) (8704 + (st) * 4096 + (sp) * 2048)
#define SB_O(st)     (16896 + (st) * 4096)
#define SMEM_U32 25088

__global__ void __launch_bounds__(256, 2)
k_gemm_mma(const uint4* __restrict__ wf,       // this layer's fragment table
           const float* __restrict__ bias,
           const float* __restrict__ nm,
           const float* __restrict__ ehin,
           float* __restrict__ ehout,
           const int* __restrict__ src,
           const int* __restrict__ rev,
           const int* __restrict__ dst,
           float* __restrict__ scat,
           int do_relu) {
    extern __shared__ float smemf[];
    uint32_t* smemu = (uint32_t*)smemf;
    int* s_src = (int*)smemf;
    int* s_rev = (int*)smemf + 128;
    int* s_dst = (int*)smemf + 256;

    const int tid = threadIdx.x;
    const int wid = tid >> 5;
    const int lid = tid & 31;
    const int mBase = blockIdx.y * TM;
    const int nBase = blockIdx.x * TN;
    const uint4* wfn = wf + (size_t)blockIdx.x * (NCHUNK * 1024); // 1024 uint4/chunk

    if (tid < TM) {
        s_src[tid] = __ldg(&src[mBase + tid]);
        s_rev[tid] = __ldg(&rev[mBase + tid]);
        s_dst[tid] = __ldg(&dst[mBase + tid]);
    }
    __syncthreads();

    const uint32_t sb = smem_u32(smemf);

    // staging coords: 8 threads per row, 16B each, 4 row-passes
    const int strow0 = tid >> 3;      // 0..31
    const int kp     = tid & 7;       // 16B granule in 128B row

    uint32_t rawDstN[4], rawDstE[4];
    const float* gsrcN[4];
    const float* gsrcE[4];
#pragma unroll
    for (int p = 0; p < 4; ++p) {
        const int row = strow0 + 32 * p;
        const int g = kp ^ (row & 7);
        rawDstN[p] = sb + (RAWNM + row * 32 + g * 4) * 4;
        rawDstE[p] = sb + (RAWEH + row * 32 + g * 4) * 4;
        gsrcN[p] = nm + (size_t)s_src[row] * D_N + kp * 4;
        gsrcE[p] = ehin + (size_t)s_rev[row] * D_N + kp * 4;
    }

    auto issue_raw = [&](int c) {
        const int ko = c * KC;
#pragma unroll
        for (int p = 0; p < 4; ++p) {
            CP_ASYNC_16(rawDstN[p], gsrcN[p] + ko);
            CP_ASYNC_16(rawDstE[p], gsrcE[p] + ko);
        }
    };
    auto issue_B = [&](int c, int st) {
        const uint32_t dbase = sb + SB_O(st) * 4;
        const uint4* sBp = wfn + c * 1024;
#pragma unroll
        for (int q = 0; q < 4; ++q) {
            const int i = tid + q * 256;
            CP_ASYNC_16(dbase + i * 16, sBp + i);
        }
    };
    // convert raw -> bf16 split tiles (SA stage st)
    auto convert = [&](int st) {
        const int sa0 = SA_O(st, 0);
        const int sa1 = SA_O(st, 1);
#pragma unroll
        for (int p = 0; p < 4; ++p) {
            const int row = strow0 + 32 * p;
            const int g = kp ^ (row & 7);
            const float4 n4 = *(const float4*)(smemf + RAWNM + row * 32 + g * 4);
            const float4 e4 = *(const float4*)(smemf + RAWEH + row * 32 + g * 4);
            float em0 = n4.x - fmaxf(e4.x, 0.f);
            float em1 = n4.y - fmaxf(e4.y, 0.f);
            float em2 = n4.z - fmaxf(e4.z, 0.f);
            float em3 = n4.w - fmaxf(e4.w, 0.f);
            float2 bk;
            uint2 s0, s1;
            s0.x = pack_bf2(em0, em1, bk);
            s1.x = pack_bf2n(em0 - bk.x, em1 - bk.y);
            s0.y = pack_bf2(em2, em3, bk);
            s1.y = pack_bf2n(em2 - bk.x, em3 - bk.y);
            const int sw = ((row >> 1) & 3) << 2;
            const int off = row * 16 + ((2 * kp) ^ sw);
            *(uint2*)(smemu + sa0 + off) = s0;
            *(uint2*)(smemu + sa1 + off) = s1;
        }
    };

    // ---- warp tiles: 2 (M) x 4 (N) of 64x32 ----
    const int wm  = (wid >> 2) * 64;
    const int wnb = (wid & 3) * 4;      // nb base (each nb = 8 cols)
    const int wn  = wnb * 8;

    // ldmatrix per-lane geometry: lanes 0-15 -> rows, lanes 16-31 -> k+8 half
    const int lmrow = lid & 15;                  // row within 16-row block
    const int lmkh  = (lid >> 4) << 2;           // 0 or 4 (u32 idx)
    uint32_t lmOff[4];                           // per-rbi row offset + swizzle
    uint32_t lmSw[4];
#pragma unroll
    for (int rbi = 0; rbi < 4; ++rbi) {
        const int row = wm + rbi * 16 + lmrow;
        lmOff[rbi] = row * 16;
        lmSw[rbi]  = ((row >> 1) & 3) << 2;
    }

    float acc[4][4][4];
#pragma unroll
    for (int i = 0; i < 4; ++i)
#pragma unroll
        for (int j = 0; j < 4; ++j)
#pragma unroll
            for (int k = 0; k < 4; ++k) acc[i][j][k] = 0.f;

    // prologue: gathers + B for chunk 0 in flight
    issue_raw(0);
    issue_B(0, 0);
    CP_ASYNC_COMMIT();

    // Single-sync chunk pipeline:
    //   wait(group c) -> convert(c) -> sync -> issue(c+1) -> MMA(c)
    for (int c = 0; c < NCHUNK; ++c) {
        const int st = c & 1;
        CP_ASYNC_WAIT0();               // raw(c) + B(c) arrived
        convert(st);
        __syncthreads();
        if (c + 1 < NCHUNK) {
            issue_raw(c + 1);
            issue_B(c + 1, st ^ 1);
            CP_ASYNC_COMMIT();
        }

        // MMA on stage st (A fragments via ldmatrix.x4)
#pragma unroll
        for (int k16 = 0; k16 < 2; ++k16) {
            uint4 b[4];
#pragma unroll
            for (int nb = 0; nb < 4; ++nb)
                b[nb] = *(const uint4*)(smemu + SB_O(st) +
                         ((k16 * 16 + wnb + nb) * 32 + lid) * 4);
#pragma unroll
            for (int rbi = 0; rbi < 4; ++rbi) {
                const uint32_t idx = (uint32_t)((k16 * 8) | lmkh) ^ lmSw[rbi];
                const uint32_t a0addr =
                    sb + (SA_O(st, 0) + lmOff[rbi] + idx) * 4;
                uint32_t as0[4], as1[4];
                ldmatrix_x4(as0, a0addr);
                ldmatrix_x4(as1, a0addr + 2048 * 4);   // split-lo tile
#pragma unroll
                for (int nb = 0; nb < 4; ++nb)
                    mma_bf16(acc[rbi][nb], as0, b[nb].x, b[nb].y);
#pragma unroll
                for (int nb = 0; nb < 4; ++nb)
                    mma_bf16(acc[rbi][nb], as1, b[nb].x, b[nb].y);
#pragma unroll
                for (int nb = 0; nb < 4; ++nb)
                    mma_bf16(acc[rbi][nb], as0, b[nb].z, b[nb].w);
            }
        }
    }

    // ---- epilogue: ehout = ehin + acc + bias; fused scatter (vector RED) ----
    const int lr4 = lid >> 2;
    const int lm4 = lid & 3;
#pragma unroll
    for (int rbi = 0; rbi < 4; ++rbi) {
#pragma unroll
        for (int half = 0; half < 2; ++half) {
            const int mi = wm + rbi * 16 + half * 8 + lr4;
            const int m = mBase + mi;
            const int d = s_dst[mi];
            const float* ein = ehin + (size_t)m * D_N + nBase;
            float* eout = ehout + (size_t)m * D_N + nBase;
            float* srow = scat + (size_t)d * D_N + nBase;
#pragma unroll
            for (int nb = 0; nb < 4; ++nb) {
                const int cc = wn + nb * 8 + 2 * lm4;
                float2 e = *(const float2*)(ein + cc);
                e.x += acc[rbi][nb][half * 2 + 0] + __ldg(&bias[nBase + cc]);
                e.y += acc[rbi][nb][half * 2 + 1] + __ldg(&bias[nBase + cc + 1]);
                *(float2*)(eout + cc) = e;
                if (do_relu) {
                    red_add_v2(srow + cc, fmaxf(e.x, 0.f), fmaxf(e.y, 0.f));
                } else {
                    red_add_v2(srow + cc, e.x, e.y);
                }
            }
        }
    }
}

// ---------------------------------------------------------------------------
extern "C" void kernel_launch(void* const* d_in, const int* in_sizes, int n_in,
                              void* d_out, int out_size) {
    const float* node_feats = (const float*)d_in[0];
    const float* edge_feats = (const float*)d_in[1];
    const float* Ws         = (const float*)d_in[2];
    const float* bs         = (const float*)d_in[3];
    const int*   edge_index = (const int*)  d_in[4];
    const int*   rev_index  = (const int*)  d_in[5];

    const int* src = edge_index;
    const int* dst = edge_index + E_N;

    float* out_nodes = (float*)d_out;
    float* eh_out    = (float*)d_out + (size_t)V_N * D_N;

    float *eh_scratch = nullptr, *nm0 = nullptr, *nm1 = nullptr;
    uint4* wfrag = nullptr;
    cudaGetSymbolAddress((void**)&eh_scratch, g_eh);
    cudaGetSymbolAddress((void**)&nm0, g_nm0);
    cudaGetSymbolAddress((void**)&nm1, g_nm1);
    cudaGetSymbolAddress((void**)&wfrag, g_wfrag);

    const int smem_bytes = SMEM_U32 * 4;    // 100352
    cudaFuncSetAttribute(k_gemm_mma,
                         cudaFuncAttributeMaxDynamicSharedMemorySize, smem_bytes);

    const int TPB = 256;
    const int edgeGrid = (E_N * (D_N / 4)) / TPB;   // 80000
    const int nmGrid   = (V_N * (D_N / 4)) / TPB;   // 5000
    dim3 gemmGrid(D_N / TN, E_N / TM);              // (4, 1250)

    // W fragment precompute (all 3 layers)
    k_wfrag<<<768, 256>>>(Ws);

    k_zero_ptr<<<nmGrid, TPB>>>((float4*)nm0, V_N * D_N / 4);
    k_init_eh_scatter<<<edgeGrid, TPB>>>(node_feats, edge_feats, src, dst, nm0);

    float* ehbufs[2] = { eh_scratch, eh_out };
    float* nmbufs[2] = { nm0, nm1 };
    const int frag_per_layer = 4 * NCHUNK * 1024;   // uint4 per layer
    for (int l = 0; l < DEPTH_N; ++l) {
        const float* ehin = ehbufs[l & 1];
        float*       eho  = ehbufs[(l + 1) & 1];
        const float* nmc  = nmbufs[l & 1];
        float*       scat;
        int          do_relu;
        if (l + 1 < DEPTH_N) {
            scat = nmbufs[(l + 1) & 1];
            do_relu = 1;
            k_zero_ptr<<<nmGrid, TPB>>>((float4*)scat, V_N * D_N / 4);
        } else {
            scat = out_nodes;
            do_relu = 0;
            k_zero_ptr<<<nmGrid, TPB>>>((float4*)out_nodes, V_N * D_N / 4);
        }
        k_gemm_mma<<<gemmGrid, TPB, smem_bytes>>>(
            wfrag + (size_t)l * frag_per_layer, bs + (size_t)l * D_N,
            nmc, ehin, eho, src, rev_index, dst, scat, do_relu);
    }
}